// round 1
// baseline (speedup 1.0000x reference)
#include <cuda_runtime.h>
#include <math.h>

#define BATCH 2
#define SEQ   2048
#define DIN   1024
#define DOUT  1024
#define NH    16
#define HD    64
#define MTOT  (BATCH*SEQ)   // 4096

// scratch (no cudaMalloc allowed)
__device__ float g_Q[MTOT*DOUT];
__device__ float g_K[MTOT*DOUT];
__device__ float g_V[MTOT*DOUT];
__device__ float g_A[MTOT*DOUT];

// ---------------------------------------------------------------------------
// 64x64x16 fp32 tiled GEMM body: C = A(MxK) * B(KxN), all row-major.
// 256 threads, each computes 4x4.
// ---------------------------------------------------------------------------
__device__ __forceinline__ void gemm64_body(const float* __restrict__ A,
                                            const float* __restrict__ B,
                                            float* __restrict__ C,
                                            int M, int N, int K) {
    __shared__ float As[16][64];   // transposed: As[k][m]
    __shared__ float Bs[16][64];   // Bs[k][n]

    const int tid = threadIdx.x;
    const int tx  = tid & 15;      // 0..15  -> 4 cols each
    const int ty  = tid >> 4;      // 0..15  -> 4 rows each
    const int bm  = blockIdx.y * 64;
    const int bn  = blockIdx.x * 64;

    float acc[4][4] = {};

    const int arow = tid >> 2;     // 0..63
    const int akq  = tid & 3;      // float4 index along k
    const int brow = tid >> 4;     // 0..15
    const int bc4  = tid & 15;     // float4 index along n

    for (int kt = 0; kt < K; kt += 16) {
        float4 av = *(const float4*)&A[(size_t)(bm + arow) * K + kt + akq * 4];
        As[akq*4+0][arow] = av.x;
        As[akq*4+1][arow] = av.y;
        As[akq*4+2][arow] = av.z;
        As[akq*4+3][arow] = av.w;
        *(float4*)&Bs[brow][bc4*4] =
            *(const float4*)&B[(size_t)(kt + brow) * N + bn + bc4 * 4];
        __syncthreads();

        #pragma unroll
        for (int k = 0; k < 16; k++) {
            float4 a = *(float4*)&As[k][ty*4];
            float4 b = *(float4*)&Bs[k][tx*4];
            float ar[4] = {a.x, a.y, a.z, a.w};
            float br[4] = {b.x, b.y, b.z, b.w};
            #pragma unroll
            for (int i = 0; i < 4; i++)
                #pragma unroll
                for (int j = 0; j < 4; j++)
                    acc[i][j] += ar[i] * br[j];
        }
        __syncthreads();
    }

    #pragma unroll
    for (int i = 0; i < 4; i++) {
        float4 v = make_float4(acc[i][0], acc[i][1], acc[i][2], acc[i][3]);
        *(float4*)&C[(size_t)(bm + ty*4 + i) * N + bn + tx*4] = v;
    }
}

// QKV projections: grid (N/64, M/64, 3); z picks the weight/output.
__global__ void qkv_gemm_kernel(const float* __restrict__ x,
                                const float* __restrict__ Wq,
                                const float* __restrict__ Wk,
                                const float* __restrict__ Wv) {
    const float* B;
    float* C;
    if (blockIdx.z == 0)      { B = Wq; C = g_Q; }
    else if (blockIdx.z == 1) { B = Wk; C = g_K; }
    else                      { B = Wv; C = g_V; }
    gemm64_body(x, B, C, MTOT, DOUT, DIN);
}

// Output projection: d_out = g_A @ Wout
__global__ void out_gemm_kernel(const float* __restrict__ Wout,
                                float* __restrict__ out) {
    gemm64_body(g_A, Wout, out, MTOT, DOUT, DOUT);
}

// ---------------------------------------------------------------------------
// Causal flash attention.
// grid: (SEQ/64 q-tiles, NH, BATCH), 128 threads (tx 0..15 -> 4 dims/keys,
// ty 0..7 -> 8 rows with stride 8: r = ty + 8*i).
// Dynamic smem: Qs[64][68], KP[64][68] (K^T then P), Vs[64][64].
// ---------------------------------------------------------------------------
#define QS_STRIDE 68
#define ATTN_SMEM_FLOATS (64*QS_STRIDE + 64*QS_STRIDE + 64*64)

__global__ void attn_kernel() {
    extern __shared__ float smem[];
    float* Qs = smem;                        // [64][68] row-major (row=query)
    float* KP = Qs + 64*QS_STRIDE;           // [64][68]: K^T (Kt[d][key]) then P[row][key]
    float* Vs = KP + 64*QS_STRIDE;           // [64][64]  (Vs[key][d])

    const int qt  = blockIdx.x;
    const int h   = blockIdx.y;
    const int b   = blockIdx.z;
    const int tid = threadIdx.x;             // 0..127
    const int tx  = tid & 15;
    const int ty  = tid >> 4;                // 0..7

    const int qbase   = qt * 64;
    const int rowbase = b * SEQ;             // row offset into [4096,1024] buffers
    const int colbase = h * HD;

    // load Q tile: 64 rows x 64 dims
    #pragma unroll
    for (int t = 0; t < 8; t++) {
        int f   = tid + t * 128;             // float4 index, 0..1023
        int row = f >> 4;                    // 0..63
        int c4  = f & 15;
        float4 v = *(const float4*)&g_Q[(size_t)(rowbase + qbase + row) * DOUT + colbase + c4*4];
        *(float4*)&Qs[row * QS_STRIDE + c4*4] = v;
    }

    float o[8][4] = {};
    float m[8], l[8];
    #pragma unroll
    for (int i = 0; i < 8; i++) { m[i] = -1e30f; l[i] = 0.f; }

    const unsigned FULL = 0xffffffffu;

    for (int kt = 0; kt <= qt; kt++) {
        __syncthreads();  // prior O-phase reads of KP/Vs complete

        // load K tile transposed, V tile direct
        const int kbase = kt * 64;
        #pragma unroll
        for (int t = 0; t < 8; t++) {
            int f   = tid + t * 128;
            int row = f >> 4;                // key index
            int c4  = f & 15;
            float4 kv = *(const float4*)&g_K[(size_t)(rowbase + kbase + row) * DOUT + colbase + c4*4];
            KP[(c4*4+0) * QS_STRIDE + row] = kv.x;
            KP[(c4*4+1) * QS_STRIDE + row] = kv.y;
            KP[(c4*4+2) * QS_STRIDE + row] = kv.z;
            KP[(c4*4+3) * QS_STRIDE + row] = kv.w;
            float4 vv = *(const float4*)&g_V[(size_t)(rowbase + kbase + row) * DOUT + colbase + c4*4];
            *(float4*)&Vs[row * 64 + c4*4] = vv;
        }
        __syncthreads();

        // S = Q * K^T  (acc[i][j]: row ty+8i, key tx*4+j)
        float acc[8][4] = {};
        #pragma unroll 4
        for (int kk = 0; kk < 64; kk++) {
            float a[8];
            #pragma unroll
            for (int i = 0; i < 8; i++)
                a[i] = Qs[(ty + 8*i) * QS_STRIDE + kk];
            float4 bv = *(float4*)&KP[kk * QS_STRIDE + tx*4];
            float br[4] = {bv.x, bv.y, bv.z, bv.w};
            #pragma unroll
            for (int i = 0; i < 8; i++)
                #pragma unroll
                for (int j = 0; j < 4; j++)
                    acc[i][j] += a[i] * br[j];
        }

        // scale, mask, online softmax (row stats replicated across 16 tx lanes)
        const bool diag = (kt == qt);
        #pragma unroll
        for (int i = 0; i < 8; i++) {
            const int qg = qbase + ty + 8*i;
            float rmax = -1e30f;
            #pragma unroll
            for (int j = 0; j < 4; j++) {
                float s = acc[i][j] * 0.125f;   // 1/sqrt(64)
                if (diag && (kt*64 + tx*4 + j) > qg) s = -1e30f;
                acc[i][j] = s;
                rmax = fmaxf(rmax, s);
            }
            #pragma unroll
            for (int sft = 1; sft < 16; sft <<= 1)
                rmax = fmaxf(rmax, __shfl_xor_sync(FULL, rmax, sft));
            float newm = fmaxf(m[i], rmax);
            float rsum = 0.f;
            #pragma unroll
            for (int j = 0; j < 4; j++) {
                float p = __expf(acc[i][j] - newm);
                acc[i][j] = p;
                rsum += p;
            }
            #pragma unroll
            for (int sft = 1; sft < 16; sft <<= 1)
                rsum += __shfl_xor_sync(FULL, rsum, sft);
            float alpha = __expf(m[i] - newm);
            l[i] = l[i] * alpha + rsum;
            m[i] = newm;
            #pragma unroll
            for (int j = 0; j < 4; j++)
                o[i][j] *= alpha;
        }

        __syncthreads();  // all S reads of KP done before overwrite with P
        #pragma unroll
        for (int i = 0; i < 8; i++) {
            float4 pv = make_float4(acc[i][0], acc[i][1], acc[i][2], acc[i][3]);
            *(float4*)&KP[(ty + 8*i) * QS_STRIDE + tx*4] = pv;
        }
        __syncthreads();

        // O += P * V  (O cols tx*4+j)
        #pragma unroll 4
        for (int kk = 0; kk < 64; kk++) {
            float p[8];
            #pragma unroll
            for (int i = 0; i < 8; i++)
                p[i] = KP[(ty + 8*i) * QS_STRIDE + kk];
            float4 vv = *(float4*)&Vs[kk * 64 + tx*4];
            float vr[4] = {vv.x, vv.y, vv.z, vv.w};
            #pragma unroll
            for (int i = 0; i < 8; i++)
                #pragma unroll
                for (int j = 0; j < 4; j++)
                    o[i][j] += p[i] * vr[j];
        }
    }

    // normalize + store to g_A[b, q, h, d] = [4096, 1024] row-major
    #pragma unroll
    for (int i = 0; i < 8; i++) {
        float inv = 1.f / l[i];
        int r = ty + 8*i;
        float4 ov = make_float4(o[i][0]*inv, o[i][1]*inv, o[i][2]*inv, o[i][3]*inv);
        *(float4*)&g_A[(size_t)(rowbase + qbase + r) * DOUT + colbase + tx*4] = ov;
    }
}

// ---------------------------------------------------------------------------
extern "C" void kernel_launch(void* const* d_in, const int* in_sizes, int n_in,
                              void* d_out, int out_size) {
    (void)in_sizes; (void)n_in; (void)out_size;
    const float* x    = (const float*)d_in[0];
    const float* Wq   = (const float*)d_in[1];
    const float* Wk   = (const float*)d_in[2];
    const float* Wv   = (const float*)d_in[3];
    const float* Wout = (const float*)d_in[4];
    float* out = (float*)d_out;

    static bool attr_set = false;
    if (!attr_set) {
        cudaFuncSetAttribute(attn_kernel,
                             cudaFuncAttributeMaxDynamicSharedMemorySize,
                             ATTN_SMEM_FLOATS * (int)sizeof(float));
        attr_set = true;
    }

    dim3 gQKV(DOUT/64, MTOT/64, 3);
    qkv_gemm_kernel<<<gQKV, 256>>>(x, Wq, Wk, Wv);

    dim3 gAttn(SEQ/64, NH, BATCH);
    attn_kernel<<<gAttn, 128, ATTN_SMEM_FLOATS * (int)sizeof(float)>>>();

    dim3 gOut(DOUT/64, MTOT/64);
    out_gemm_kernel<<<gOut, 256>>>(Wout, out);
}

// round 3
// speedup vs baseline: 1.8323x; 1.8323x over previous
#include <cuda_runtime.h>
#include <math.h>
#include <stdint.h>

#define BATCH 2
#define SEQ   2048
#define DIN   1024
#define DOUT  1024
#define NH    16
#define HD    64
#define MTOT  (BATCH*SEQ)   // 4096

// ---------------------------------------------------------------------------
// scratch (no cudaMalloc allowed)
// ---------------------------------------------------------------------------
__device__ float g_Xr[MTOT*DIN];           // x rounded to tf32
__device__ float g_Wt[4][DIN*DOUT];        // W^T [n][k], tf32-rounded (q,k,v,out)
__device__ float g_Q[MTOT*DOUT];
__device__ float g_K[MTOT*DOUT];
__device__ float g_V[MTOT*DOUT];
__device__ float g_A[MTOT*DOUT];           // attention output (tf32-rounded)

// ---------------------------------------------------------------------------
// helpers
// ---------------------------------------------------------------------------
__device__ __forceinline__ uint32_t smem_u32(const void* p) {
    return (uint32_t)__cvta_generic_to_shared(p);
}

__device__ __forceinline__ float rna_tf32(float f) {
    uint32_t u;
    asm("cvt.rna.tf32.f32 %0, %1;" : "=r"(u) : "f"(f));
    return __uint_as_float(u);
}

__device__ __forceinline__ void cp_async16(uint32_t dst, const void* src) {
    asm volatile("cp.async.cg.shared.global [%0], [%1], 16;" :: "r"(dst), "l"(src) : "memory");
}
__device__ __forceinline__ void cp_commit() {
    asm volatile("cp.async.commit_group;" ::: "memory");
}
__device__ __forceinline__ void cp_wait1() {
    asm volatile("cp.async.wait_group 1;" ::: "memory");
}

// m16n8k8 tf32 HMMA, row.col, fp32 accumulate
__device__ __forceinline__ void mma_tf32(float* d, const uint32_t* a, const uint32_t* b) {
    asm volatile(
        "mma.sync.aligned.m16n8k8.row.col.f32.tf32.tf32.f32 "
        "{%0,%1,%2,%3}, {%4,%5,%6,%7}, {%8,%9}, {%0,%1,%2,%3};"
        : "+f"(d[0]), "+f"(d[1]), "+f"(d[2]), "+f"(d[3])
        : "r"(a[0]), "r"(a[1]), "r"(a[2]), "r"(a[3]), "r"(b[0]), "r"(b[1]));
}

// ---------------------------------------------------------------------------
// prep kernels
// ---------------------------------------------------------------------------
__global__ void round_x_kernel(const float* __restrict__ x) {
    int i = blockIdx.x * 256 + threadIdx.x;     // 1M float4
    float4 v = ((const float4*)x)[i];
    v.x = rna_tf32(v.x); v.y = rna_tf32(v.y);
    v.z = rna_tf32(v.z); v.w = rna_tf32(v.w);
    ((float4*)g_Xr)[i] = v;
}

// transpose + round: g_Wt[z][n*1024+k] = rna(W[k*1024+n])
__global__ void wtrans_kernel(const float* __restrict__ Wq,
                              const float* __restrict__ Wk,
                              const float* __restrict__ Wv,
                              const float* __restrict__ Wo) {
    __shared__ float t[32][33];
    const float* W = (blockIdx.z == 0) ? Wq : (blockIdx.z == 1) ? Wk
                   : (blockIdx.z == 2) ? Wv : Wo;
    float* out = g_Wt[blockIdx.z];
    int n0 = blockIdx.x * 32, k0 = blockIdx.y * 32;
    int tx = threadIdx.x, ty = threadIdx.y;   // 32 x 8
    #pragma unroll
    for (int i = 0; i < 4; i++)
        t[ty + 8*i][tx] = W[(size_t)(k0 + ty + 8*i) * DOUT + n0 + tx];
    __syncthreads();
    #pragma unroll
    for (int i = 0; i < 4; i++)
        out[(size_t)(n0 + ty + 8*i) * DIN + k0 + tx] = rna_tf32(t[tx][ty + 8*i]);
}

// ---------------------------------------------------------------------------
// HMMA tf32 GEMM: C = A[M,1024] @ Bt[N,1024]^T, 128x128 CTA tile, 256 threads.
// 8 warps = 4(m) x 2(n), warp tile 32x64. BK=32, double-buffered cp.async.
// smem stride 36 floats: fragment loads hit banks 4r+c -> conflict-free.
// ---------------------------------------------------------------------------
#define AST 36
#define STG_FLOATS (128*AST)
#define GEMM_SMEM  (2*2*STG_FLOATS*4)     // 73728 bytes

__device__ __forceinline__ void g_load_stage(const float* __restrict__ A,
                                             const float* __restrict__ Bt,
                                             uint32_t sA, uint32_t sB,
                                             int stage, int kc, int bm, int bn, int tid) {
    const float* srcA = A  + (size_t)bm * DIN + kc * 32;
    const float* srcB = Bt + (size_t)bn * DIN + kc * 32;
    const uint32_t dA = sA + stage * STG_FLOATS * 4;
    const uint32_t dB = sB + stage * STG_FLOATS * 4;
    #pragma unroll
    for (int i = 0; i < 4; i++) {
        int idx = tid + i * 256;        // 0..1023
        int row = idx >> 3, c4 = idx & 7;
        uint32_t off = (row * AST + c4 * 4) * 4;
        cp_async16(dA + off, srcA + (size_t)row * DIN + c4 * 4);
        cp_async16(dB + off, srcB + (size_t)row * DIN + c4 * 4);
    }
}

__device__ __forceinline__ void gemm_tile_body(const float* __restrict__ A,
                                               const float* __restrict__ Bt,
                                               float* __restrict__ C) {
    extern __shared__ float smem[];
    float* sA = smem;                       // [2][128][36]
    float* sB = smem + 2 * STG_FLOATS;      // [2][128][36]
    const uint32_t sAu = smem_u32(sA);
    const uint32_t sBu = smem_u32(sB);

    const int tid  = threadIdx.x;
    const int lane = tid & 31;
    const int wid  = tid >> 5;
    const int wm   = wid >> 1;              // 0..3
    const int wn   = wid & 1;               // 0..1
    const int bm   = blockIdx.y * 128;
    const int bn   = blockIdx.x * 128;
    const int r    = lane >> 2;             // 0..7
    const int c    = lane & 3;              // 0..3

    float acc[16][4] = {};                  // [i*8+j][reg]

    const int NKC = DIN / 32;               // 32 chunks

    g_load_stage(A, Bt, sAu, sBu, 0, 0, bm, bn, tid);
    cp_commit();

    for (int kc = 0; kc < NKC; kc++) {
        if (kc + 1 < NKC)
            g_load_stage(A, Bt, sAu, sBu, (kc + 1) & 1, kc + 1, bm, bn, tid);
        cp_commit();
        cp_wait1();                 // chunk kc resident
        __syncthreads();

        const float* cA = sA + (kc & 1) * STG_FLOATS;
        const float* cB = sB + (kc & 1) * STG_FLOATS;

        #pragma unroll
        for (int ks = 0; ks < 4; ks++) {
            const int k0 = ks * 8;
            uint32_t a[2][4];
            #pragma unroll
            for (int i = 0; i < 2; i++) {
                const float* ab = cA + (wm * 32 + i * 16 + r) * AST + k0 + c;
                a[i][0] = __float_as_uint(ab[0]);
                a[i][1] = __float_as_uint(ab[8 * AST]);
                a[i][2] = __float_as_uint(ab[4]);
                a[i][3] = __float_as_uint(ab[8 * AST + 4]);
            }
            #pragma unroll
            for (int j = 0; j < 8; j++) {
                const float* bb = cB + (wn * 64 + j * 8 + r) * AST + k0 + c;
                uint32_t b[2] = { __float_as_uint(bb[0]), __float_as_uint(bb[4]) };
                mma_tf32(acc[j],     a[0], b);
                mma_tf32(acc[8 + j], a[1], b);
            }
        }
        __syncthreads();
    }

    // epilogue: d0:(r, 2c) d1:(r, 2c+1) d2:(r+8, 2c) d3:(r+8, 2c+1)
    #pragma unroll
    for (int i = 0; i < 2; i++) {
        const int row = bm + wm * 32 + i * 16 + r;
        #pragma unroll
        for (int j = 0; j < 8; j++) {
            const int col = bn + wn * 64 + j * 8 + c * 2;
            float* p0 = C + (size_t)row * DOUT + col;
            float* p1 = C + (size_t)(row + 8) * DOUT + col;
            *(float2*)p0 = make_float2(acc[i*8+j][0], acc[i*8+j][1]);
            *(float2*)p1 = make_float2(acc[i*8+j][2], acc[i*8+j][3]);
        }
    }
}

__global__ void __launch_bounds__(256) qkv_mma_kernel() {
    float* C = (blockIdx.z == 0) ? g_Q : (blockIdx.z == 1) ? g_K : g_V;
    gemm_tile_body(g_Xr, g_Wt[blockIdx.z], C);
}

__global__ void __launch_bounds__(256) out_mma_kernel(float* __restrict__ out) {
    gemm_tile_body(g_A, g_Wt[3], out);
}

// ---------------------------------------------------------------------------
// Causal flash attention (R1, proven). Output store tf32-rounded for out-GEMM.
// ---------------------------------------------------------------------------
#define QS_STRIDE 68
#define ATTN_SMEM_FLOATS (64*QS_STRIDE + 64*QS_STRIDE + 64*64)

__global__ void attn_kernel() {
    extern __shared__ float smem[];
    float* Qs = smem;
    float* KP = Qs + 64*QS_STRIDE;
    float* Vs = KP + 64*QS_STRIDE;

    const int qt  = blockIdx.x;
    const int h   = blockIdx.y;
    const int b   = blockIdx.z;
    const int tid = threadIdx.x;
    const int tx  = tid & 15;
    const int ty  = tid >> 4;

    const int qbase   = qt * 64;
    const int rowbase = b * SEQ;
    const int colbase = h * HD;

    #pragma unroll
    for (int t = 0; t < 8; t++) {
        int f   = tid + t * 128;
        int row = f >> 4;
        int c4  = f & 15;
        float4 v = *(const float4*)&g_Q[(size_t)(rowbase + qbase + row) * DOUT + colbase + c4*4];
        *(float4*)&Qs[row * QS_STRIDE + c4*4] = v;
    }

    float o[8][4] = {};
    float m[8], l[8];
    #pragma unroll
    for (int i = 0; i < 8; i++) { m[i] = -1e30f; l[i] = 0.f; }

    const unsigned FULL = 0xffffffffu;

    for (int kt = 0; kt <= qt; kt++) {
        __syncthreads();
        const int kbase = kt * 64;
        #pragma unroll
        for (int t = 0; t < 8; t++) {
            int f   = tid + t * 128;
            int row = f >> 4;
            int c4  = f & 15;
            float4 kv = *(const float4*)&g_K[(size_t)(rowbase + kbase + row) * DOUT + colbase + c4*4];
            KP[(c4*4+0) * QS_STRIDE + row] = kv.x;
            KP[(c4*4+1) * QS_STRIDE + row] = kv.y;
            KP[(c4*4+2) * QS_STRIDE + row] = kv.z;
            KP[(c4*4+3) * QS_STRIDE + row] = kv.w;
            float4 vv = *(const float4*)&g_V[(size_t)(rowbase + kbase + row) * DOUT + colbase + c4*4];
            *(float4*)&Vs[row * 64 + c4*4] = vv;
        }
        __syncthreads();

        float acc[8][4] = {};
        #pragma unroll 4
        for (int kk = 0; kk < 64; kk++) {
            float a[8];
            #pragma unroll
            for (int i = 0; i < 8; i++)
                a[i] = Qs[(ty + 8*i) * QS_STRIDE + kk];
            float4 bv = *(float4*)&KP[kk * QS_STRIDE + tx*4];
            float br[4] = {bv.x, bv.y, bv.z, bv.w};
            #pragma unroll
            for (int i = 0; i < 8; i++)
                #pragma unroll
                for (int j = 0; j < 4; j++)
                    acc[i][j] += a[i] * br[j];
        }

        const bool diag = (kt == qt);
        #pragma unroll
        for (int i = 0; i < 8; i++) {
            const int qg = qbase + ty + 8*i;
            float rmax = -1e30f;
            #pragma unroll
            for (int j = 0; j < 4; j++) {
                float s = acc[i][j] * 0.125f;
                if (diag && (kt*64 + tx*4 + j) > qg) s = -1e30f;
                acc[i][j] = s;
                rmax = fmaxf(rmax, s);
            }
            #pragma unroll
            for (int sft = 1; sft < 16; sft <<= 1)
                rmax = fmaxf(rmax, __shfl_xor_sync(FULL, rmax, sft));
            float newm = fmaxf(m[i], rmax);
            float rsum = 0.f;
            #pragma unroll
            for (int j = 0; j < 4; j++) {
                float p = __expf(acc[i][j] - newm);
                acc[i][j] = p;
                rsum += p;
            }
            #pragma unroll
            for (int sft = 1; sft < 16; sft <<= 1)
                rsum += __shfl_xor_sync(FULL, rsum, sft);
            float alpha = __expf(m[i] - newm);
            l[i] = l[i] * alpha + rsum;
            m[i] = newm;
            #pragma unroll
            for (int j = 0; j < 4; j++)
                o[i][j] *= alpha;
        }

        __syncthreads();
        #pragma unroll
        for (int i = 0; i < 8; i++) {
            float4 pv = make_float4(acc[i][0], acc[i][1], acc[i][2], acc[i][3]);
            *(float4*)&KP[(ty + 8*i) * QS_STRIDE + tx*4] = pv;
        }
        __syncthreads();

        #pragma unroll 4
        for (int kk = 0; kk < 64; kk++) {
            float p[8];
            #pragma unroll
            for (int i = 0; i < 8; i++)
                p[i] = KP[(ty + 8*i) * QS_STRIDE + kk];
            float4 vv = *(float4*)&Vs[kk * 64 + tx*4];
            float vr[4] = {vv.x, vv.y, vv.z, vv.w};
            #pragma unroll
            for (int i = 0; i < 8; i++)
                #pragma unroll
                for (int j = 0; j < 4; j++)
                    o[i][j] += p[i] * vr[j];
        }
    }

    #pragma unroll
    for (int i = 0; i < 8; i++) {
        float inv = 1.f / l[i];
        int r = ty + 8*i;
        float4 ov = make_float4(rna_tf32(o[i][0]*inv), rna_tf32(o[i][1]*inv),
                                rna_tf32(o[i][2]*inv), rna_tf32(o[i][3]*inv));
        *(float4*)&g_A[(size_t)(rowbase + qbase + r) * DOUT + colbase + tx*4] = ov;
    }
}

// ---------------------------------------------------------------------------
extern "C" void kernel_launch(void* const* d_in, const int* in_sizes, int n_in,
                              void* d_out, int out_size) {
    (void)in_sizes; (void)n_in; (void)out_size;
    const float* x    = (const float*)d_in[0];
    const float* Wq   = (const float*)d_in[1];
    const float* Wk   = (const float*)d_in[2];
    const float* Wv   = (const float*)d_in[3];
    const float* Wout = (const float*)d_in[4];
    float* out = (float*)d_out;

    static bool attr_set = false;
    if (!attr_set) {
        cudaFuncSetAttribute(attn_kernel,
                             cudaFuncAttributeMaxDynamicSharedMemorySize,
                             ATTN_SMEM_FLOATS * (int)sizeof(float));
        cudaFuncSetAttribute(qkv_mma_kernel,
                             cudaFuncAttributeMaxDynamicSharedMemorySize, GEMM_SMEM);
        cudaFuncSetAttribute(out_mma_kernel,
                             cudaFuncAttributeMaxDynamicSharedMemorySize, GEMM_SMEM);
        attr_set = true;
    }

    round_x_kernel<<<(MTOT*DIN)/(256*4), 256>>>(x);
    wtrans_kernel<<<dim3(DOUT/32, DIN/32, 4), dim3(32, 8)>>>(Wq, Wk, Wv, Wout);

    qkv_mma_kernel<<<dim3(DOUT/128, MTOT/128, 3), 256, GEMM_SMEM>>>();

    attn_kernel<<<dim3(SEQ/64, NH, BATCH), 128, ATTN_SMEM_FLOATS * (int)sizeof(float)>>>();

    out_mma_kernel<<<dim3(DOUT/128, MTOT/128), 256, GEMM_SMEM>>>(out);
}

// round 4
// speedup vs baseline: 3.1130x; 1.6989x over previous
#include <cuda_runtime.h>
#include <math.h>
#include <stdint.h>

#define BATCH 2
#define SEQ   2048
#define DIN   1024
#define DOUT  1024
#define NH    16
#define HD    64
#define MTOT  (BATCH*SEQ)   // 4096

// ---------------------------------------------------------------------------
// scratch (no cudaMalloc allowed)
// ---------------------------------------------------------------------------
__device__ float g_Xr[MTOT*DIN];           // x rounded to tf32
__device__ float g_Wt[4][DIN*DOUT];        // W^T [n][k], tf32-rounded (q,k,v,out)
__device__ float g_Q[MTOT*DOUT];           // tf32-rounded
__device__ float g_K[MTOT*DOUT];           // tf32-rounded
__device__ float g_Vt[BATCH*NH*HD*SEQ];    // V transposed [b,h,d,s], tf32-rounded
__device__ float g_A[MTOT*DOUT];           // attention output (tf32-rounded)

// ---------------------------------------------------------------------------
// helpers
// ---------------------------------------------------------------------------
__device__ __forceinline__ uint32_t smem_u32(const void* p) {
    return (uint32_t)__cvta_generic_to_shared(p);
}

__device__ __forceinline__ float rna_tf32(float f) {
    uint32_t u;
    asm("cvt.rna.tf32.f32 %0, %1;" : "=r"(u) : "f"(f));
    return __uint_as_float(u);
}

__device__ __forceinline__ void cp_async16(uint32_t dst, const void* src) {
    asm volatile("cp.async.cg.shared.global [%0], [%1], 16;" :: "r"(dst), "l"(src) : "memory");
}
__device__ __forceinline__ void cp_commit() {
    asm volatile("cp.async.commit_group;" ::: "memory");
}
__device__ __forceinline__ void cp_wait1() {
    asm volatile("cp.async.wait_group 1;" ::: "memory");
}

// m16n8k8 tf32 HMMA, row.col, fp32 accumulate
__device__ __forceinline__ void mma_tf32(float* d, const uint32_t* a, const uint32_t* b) {
    asm volatile(
        "mma.sync.aligned.m16n8k8.row.col.f32.tf32.tf32.f32 "
        "{%0,%1,%2,%3}, {%4,%5,%6,%7}, {%8,%9}, {%0,%1,%2,%3};"
        : "+f"(d[0]), "+f"(d[1]), "+f"(d[2]), "+f"(d[3])
        : "r"(a[0]), "r"(a[1]), "r"(a[2]), "r"(a[3]), "r"(b[0]), "r"(b[1]));
}

// ---------------------------------------------------------------------------
// prep kernels
// ---------------------------------------------------------------------------
__global__ void round_x_kernel(const float* __restrict__ x) {
    int i = blockIdx.x * 256 + threadIdx.x;     // 1M float4
    float4 v = ((const float4*)x)[i];
    v.x = rna_tf32(v.x); v.y = rna_tf32(v.y);
    v.z = rna_tf32(v.z); v.w = rna_tf32(v.w);
    ((float4*)g_Xr)[i] = v;
}

// transpose + round: g_Wt[z][n*1024+k] = rna(W[k*1024+n])
__global__ void wtrans_kernel(const float* __restrict__ Wq,
                              const float* __restrict__ Wk,
                              const float* __restrict__ Wv,
                              const float* __restrict__ Wo) {
    __shared__ float t[32][33];
    const float* W = (blockIdx.z == 0) ? Wq : (blockIdx.z == 1) ? Wk
                   : (blockIdx.z == 2) ? Wv : Wo;
    float* out = g_Wt[blockIdx.z];
    int n0 = blockIdx.x * 32, k0 = blockIdx.y * 32;
    int tx = threadIdx.x, ty = threadIdx.y;   // 32 x 8
    #pragma unroll
    for (int i = 0; i < 4; i++)
        t[ty + 8*i][tx] = W[(size_t)(k0 + ty + 8*i) * DOUT + n0 + tx];
    __syncthreads();
    #pragma unroll
    for (int i = 0; i < 4; i++)
        out[(size_t)(n0 + ty + 8*i) * DIN + k0 + tx] = rna_tf32(t[tx][ty + 8*i]);
}

// ---------------------------------------------------------------------------
// HMMA tf32 GEMM: C = A[M,1024] @ Bt[N,1024]^T, 128x128 CTA tile, 256 threads.
// 8 warps = 4(m) x 2(n), warp tile 32x64. BK=32, double-buffered cp.async.
// EPI: 0 = plain fp32, 1 = tf32-rounded, 2 = tf32-rounded + V-transposed store
// ---------------------------------------------------------------------------
#define AST 36
#define STG_FLOATS (128*AST)
#define GEMM_SMEM  (2*2*STG_FLOATS*4)     // 73728 bytes

__device__ __forceinline__ void g_load_stage(const float* __restrict__ A,
                                             const float* __restrict__ Bt,
                                             uint32_t sA, uint32_t sB,
                                             int stage, int kc, int bm, int bn, int tid) {
    const float* srcA = A  + (size_t)bm * DIN + kc * 32;
    const float* srcB = Bt + (size_t)bn * DIN + kc * 32;
    const uint32_t dA = sA + stage * STG_FLOATS * 4;
    const uint32_t dB = sB + stage * STG_FLOATS * 4;
    #pragma unroll
    for (int i = 0; i < 4; i++) {
        int idx = tid + i * 256;        // 0..1023
        int row = idx >> 3, c4 = idx & 7;
        uint32_t off = (row * AST + c4 * 4) * 4;
        cp_async16(dA + off, srcA + (size_t)row * DIN + c4 * 4);
        cp_async16(dB + off, srcB + (size_t)row * DIN + c4 * 4);
    }
}

template<int EPI>
__device__ __forceinline__ void gemm_tile_body(const float* __restrict__ A,
                                               const float* __restrict__ Bt,
                                               float* __restrict__ C) {
    extern __shared__ float smem[];
    float* sA = smem;                       // [2][128][36]
    float* sB = smem + 2 * STG_FLOATS;      // [2][128][36]
    const uint32_t sAu = smem_u32(sA);
    const uint32_t sBu = smem_u32(sB);

    const int tid  = threadIdx.x;
    const int lane = tid & 31;
    const int wid  = tid >> 5;
    const int wm   = wid >> 1;              // 0..3
    const int wn   = wid & 1;               // 0..1
    const int bm   = blockIdx.y * 128;
    const int bn   = blockIdx.x * 128;
    const int r    = lane >> 2;             // 0..7
    const int c    = lane & 3;              // 0..3

    float acc[16][4] = {};                  // [i*8+j][reg]

    const int NKC = DIN / 32;               // 32 chunks

    g_load_stage(A, Bt, sAu, sBu, 0, 0, bm, bn, tid);
    cp_commit();

    for (int kc = 0; kc < NKC; kc++) {
        if (kc + 1 < NKC)
            g_load_stage(A, Bt, sAu, sBu, (kc + 1) & 1, kc + 1, bm, bn, tid);
        cp_commit();
        cp_wait1();                 // chunk kc resident
        __syncthreads();

        const float* cA = sA + (kc & 1) * STG_FLOATS;
        const float* cB = sB + (kc & 1) * STG_FLOATS;

        #pragma unroll
        for (int ks = 0; ks < 4; ks++) {
            const int k0 = ks * 8;
            uint32_t a[2][4];
            #pragma unroll
            for (int i = 0; i < 2; i++) {
                const float* ab = cA + (wm * 32 + i * 16 + r) * AST + k0 + c;
                a[i][0] = __float_as_uint(ab[0]);
                a[i][1] = __float_as_uint(ab[8 * AST]);
                a[i][2] = __float_as_uint(ab[4]);
                a[i][3] = __float_as_uint(ab[8 * AST + 4]);
            }
            #pragma unroll
            for (int j = 0; j < 8; j++) {
                const float* bb = cB + (wn * 64 + j * 8 + r) * AST + k0 + c;
                uint32_t b[2] = { __float_as_uint(bb[0]), __float_as_uint(bb[4]) };
                mma_tf32(acc[j],     a[0], b);
                mma_tf32(acc[8 + j], a[1], b);
            }
        }
        __syncthreads();
    }

    // epilogue: d0:(r, 2c) d1:(r, 2c+1) d2:(r+8, 2c) d3:(r+8, 2c+1)
    #pragma unroll
    for (int i = 0; i < 2; i++) {
        const int row = bm + wm * 32 + i * 16 + r;
        #pragma unroll
        for (int j = 0; j < 8; j++) {
            const int col = bn + wn * 64 + j * 8 + c * 2;
            float v0 = acc[i*8+j][0], v1 = acc[i*8+j][1];
            float v2 = acc[i*8+j][2], v3 = acc[i*8+j][3];
            if (EPI == 0) {
                *(float2*)(C + (size_t)row * DOUT + col)       = make_float2(v0, v1);
                *(float2*)(C + (size_t)(row + 8) * DOUT + col) = make_float2(v2, v3);
            } else if (EPI == 1) {
                *(float2*)(C + (size_t)row * DOUT + col)       = make_float2(rna_tf32(v0), rna_tf32(v1));
                *(float2*)(C + (size_t)(row + 8) * DOUT + col) = make_float2(rna_tf32(v2), rna_tf32(v3));
            } else {
                // transposed: g_Vt[((b*NH+h)*HD + d)*SEQ + s], h=col>>6, d=col&63
                const int bidx0 = row >> 11,  s0 = row & 2047;
                const int bidx1 = (row+8) >> 11, s1 = (row+8) & 2047;
                #pragma unroll
                for (int q = 0; q < 2; q++) {
                    const int cc = col + q;
                    const size_t base = ((size_t)((cc >> 6) + 0) * HD + (cc & 63)) * SEQ;
                    C[((size_t)bidx0 * NH * HD) * SEQ + base + s0] = rna_tf32(q ? v1 : v0);
                    C[((size_t)bidx1 * NH * HD) * SEQ + base + s1] = rna_tf32(q ? v3 : v2);
                }
            }
        }
    }
}

__global__ void __launch_bounds__(256) qkv_mma_kernel() {
    if (blockIdx.z == 0)      gemm_tile_body<1>(g_Xr, g_Wt[0], g_Q);
    else if (blockIdx.z == 1) gemm_tile_body<1>(g_Xr, g_Wt[1], g_K);
    else                      gemm_tile_body<2>(g_Xr, g_Wt[2], g_Vt);
}

__global__ void __launch_bounds__(256) out_mma_kernel(float* __restrict__ out) {
    gemm_tile_body<0>(g_A, g_Wt[3], out);
}

// ---------------------------------------------------------------------------
// Tensor-core causal flash attention.
// grid (16 qtiles reversed, NH, BATCH), 256 threads = 8 warps x 16 rows.
// Key blocks of 64. smem: sQ[128][68] sK[64][68] sVt[64][68] sP[128][68].
// ---------------------------------------------------------------------------
#define AT 68
#define ATTN_SMEM (AT*384*4)     // 104448 bytes

__global__ void __launch_bounds__(256, 2) attn_mma_kernel() {
    extern __shared__ float smem[];
    float* sQ  = smem;               // [128][AT]
    float* sK  = sQ + 128*AT;        // [64][AT]
    float* sVt = sK + 64*AT;         // [64][AT]  (rows = dims)
    float* sP  = sVt + 64*AT;        // [128][AT]

    const int qt  = 15 - blockIdx.x;   // long CTAs first
    const int h   = blockIdx.y;
    const int b   = blockIdx.z;
    const int tid = threadIdx.x;
    const int lane = tid & 31;
    const int wid  = tid >> 5;
    const int r = lane >> 2, c = lane & 3;

    const int qbase = qt * 128;
    const size_t rowbase = (size_t)b * SEQ;
    const int colbase = h * HD;
    const float* Vt = g_Vt + (size_t)(b * NH + h) * HD * SEQ;

    // load Q tile 128x64 (already tf32-rounded)
    #pragma unroll
    for (int i = 0; i < 8; i++) {
        int idx = tid + i * 256;
        int row = idx >> 4, c4 = idx & 15;
        float4 v = *(const float4*)&g_Q[(rowbase + qbase + row) * DOUT + colbase + c4*4];
        *(float4*)&sQ[row * AT + c4*4] = v;
    }

    float o[8][4] = {};
    float m0 = -1e30f, m1 = -1e30f, l0 = 0.f, l1 = 0.f;

    const int wrow = wid * 16;
    const int qg0 = qbase + wrow + r;
    const int qg1 = qg0 + 8;
    const unsigned FULL = 0xffffffffu;

    const int nkb = 2 * qt + 2;
    for (int kb = 0; kb < nkb; kb++) {
        __syncthreads();
        const int kbase = kb * 64;
        #pragma unroll
        for (int i = 0; i < 4; i++) {
            int idx = tid + i * 256;
            int row = idx >> 4, c4 = idx & 15;
            float4 kv = *(const float4*)&g_K[(rowbase + kbase + row) * DOUT + colbase + c4*4];
            *(float4*)&sK[row * AT + c4*4] = kv;
            float4 vv = *(const float4*)&Vt[(size_t)row * SEQ + kbase + c4*4];
            *(float4*)&sVt[row * AT + c4*4] = vv;
        }
        __syncthreads();

        // S = Q K^T : warp rows wrow..wrow+15, 8 n-tiles of 8 keys
        float s[8][4] = {};
        #pragma unroll
        for (int ks = 0; ks < 8; ks++) {
            const float* ap = &sQ[(wrow + r) * AT + ks*8 + c];
            uint32_t a[4] = { __float_as_uint(ap[0]),      __float_as_uint(ap[8*AT]),
                              __float_as_uint(ap[4]),      __float_as_uint(ap[8*AT+4]) };
            #pragma unroll
            for (int j = 0; j < 8; j++) {
                const float* bp = &sK[(j*8 + r) * AT + ks*8 + c];
                uint32_t bf[2] = { __float_as_uint(bp[0]), __float_as_uint(bp[4]) };
                mma_tf32(s[j], a, bf);
            }
        }

        // scale + causal mask + row max
        float rx0 = -1e30f, rx1 = -1e30f;
        #pragma unroll
        for (int j = 0; j < 8; j++) {
            int col0 = kbase + j*8 + 2*c;
            s[j][0] = (col0     <= qg0) ? s[j][0] * 0.125f : -1e30f;
            s[j][1] = (col0 + 1 <= qg0) ? s[j][1] * 0.125f : -1e30f;
            s[j][2] = (col0     <= qg1) ? s[j][2] * 0.125f : -1e30f;
            s[j][3] = (col0 + 1 <= qg1) ? s[j][3] * 0.125f : -1e30f;
            rx0 = fmaxf(rx0, fmaxf(s[j][0], s[j][1]));
            rx1 = fmaxf(rx1, fmaxf(s[j][2], s[j][3]));
        }
        rx0 = fmaxf(rx0, __shfl_xor_sync(FULL, rx0, 1));
        rx0 = fmaxf(rx0, __shfl_xor_sync(FULL, rx0, 2));
        rx1 = fmaxf(rx1, __shfl_xor_sync(FULL, rx1, 1));
        rx1 = fmaxf(rx1, __shfl_xor_sync(FULL, rx1, 2));

        float nm0 = fmaxf(m0, rx0), nm1 = fmaxf(m1, rx1);
        float sum0 = 0.f, sum1 = 0.f;
        #pragma unroll
        for (int j = 0; j < 8; j++) {
            s[j][0] = __expf(s[j][0] - nm0);
            s[j][1] = __expf(s[j][1] - nm0);
            s[j][2] = __expf(s[j][2] - nm1);
            s[j][3] = __expf(s[j][3] - nm1);
            sum0 += s[j][0] + s[j][1];
            sum1 += s[j][2] + s[j][3];
        }
        sum0 += __shfl_xor_sync(FULL, sum0, 1);
        sum0 += __shfl_xor_sync(FULL, sum0, 2);
        sum1 += __shfl_xor_sync(FULL, sum1, 1);
        sum1 += __shfl_xor_sync(FULL, sum1, 2);

        float a0 = __expf(m0 - nm0), a1 = __expf(m1 - nm1);
        l0 = l0 * a0 + sum0;  l1 = l1 * a1 + sum1;
        m0 = nm0;  m1 = nm1;
        #pragma unroll
        for (int j = 0; j < 8; j++) {
            o[j][0] *= a0; o[j][1] *= a0;
            o[j][2] *= a1; o[j][3] *= a1;
        }

        // store P (rounded) to warp-private rows of sP
        #pragma unroll
        for (int j = 0; j < 8; j++) {
            *(float2*)&sP[(wrow + r) * AT + j*8 + 2*c] =
                make_float2(rna_tf32(s[j][0]), rna_tf32(s[j][1]));
            *(float2*)&sP[(wrow + r + 8) * AT + j*8 + 2*c] =
                make_float2(rna_tf32(s[j][2]), rna_tf32(s[j][3]));
        }
        __syncwarp();

        // O += P V : k = 64 keys, B = Vt[dim][key]
        #pragma unroll
        for (int ks = 0; ks < 8; ks++) {
            const float* ap = &sP[(wrow + r) * AT + ks*8 + c];
            uint32_t a[4] = { __float_as_uint(ap[0]),      __float_as_uint(ap[8*AT]),
                              __float_as_uint(ap[4]),      __float_as_uint(ap[8*AT+4]) };
            #pragma unroll
            for (int j = 0; j < 8; j++) {
                const float* bp = &sVt[(j*8 + r) * AT + ks*8 + c];
                uint32_t bf[2] = { __float_as_uint(bp[0]), __float_as_uint(bp[4]) };
                mma_tf32(o[j], a, bf);
            }
        }
    }

    // normalize + store tf32-rounded
    const float inv0 = 1.f / l0, inv1 = 1.f / l1;
    #pragma unroll
    for (int j = 0; j < 8; j++) {
        const int col = colbase + j*8 + 2*c;
        *(float2*)&g_A[(rowbase + qbase + wrow + r) * DOUT + col] =
            make_float2(rna_tf32(o[j][0] * inv0), rna_tf32(o[j][1] * inv0));
        *(float2*)&g_A[(rowbase + qbase + wrow + r + 8) * DOUT + col] =
            make_float2(rna_tf32(o[j][2] * inv1), rna_tf32(o[j][3] * inv1));
    }
}

// ---------------------------------------------------------------------------
extern "C" void kernel_launch(void* const* d_in, const int* in_sizes, int n_in,
                              void* d_out, int out_size) {
    (void)in_sizes; (void)n_in; (void)out_size;
    const float* x    = (const float*)d_in[0];
    const float* Wq   = (const float*)d_in[1];
    const float* Wk   = (const float*)d_in[2];
    const float* Wv   = (const float*)d_in[3];
    const float* Wout = (const float*)d_in[4];
    float* out = (float*)d_out;

    static bool attr_set = false;
    if (!attr_set) {
        cudaFuncSetAttribute(attn_mma_kernel,
                             cudaFuncAttributeMaxDynamicSharedMemorySize, ATTN_SMEM);
        cudaFuncSetAttribute(qkv_mma_kernel,
                             cudaFuncAttributeMaxDynamicSharedMemorySize, GEMM_SMEM);
        cudaFuncSetAttribute(out_mma_kernel,
                             cudaFuncAttributeMaxDynamicSharedMemorySize, GEMM_SMEM);
        attr_set = true;
    }

    round_x_kernel<<<(MTOT*DIN)/(256*4), 256>>>(x);
    wtrans_kernel<<<dim3(DOUT/32, DIN/32, 4), dim3(32, 8)>>>(Wq, Wk, Wv, Wout);

    qkv_mma_kernel<<<dim3(DOUT/128, MTOT/128, 3), 256, GEMM_SMEM>>>();

    attn_mma_kernel<<<dim3(SEQ/128, NH, BATCH), 256, ATTN_SMEM>>>();

    out_mma_kernel<<<dim3(DOUT/128, MTOT/128), 256, GEMM_SMEM>>>(out);
}

// round 5
// speedup vs baseline: 5.8037x; 1.8643x over previous
#include <cuda_runtime.h>
#include <cuda_fp16.h>
#include <math.h>
#include <stdint.h>

#define BATCH 2
#define SEQ   2048
#define DIN   1024
#define DOUT  1024
#define NH    16
#define HD    64
#define MTOT  (BATCH*SEQ)   // 4096

// ---------------------------------------------------------------------------
// scratch (no cudaMalloc allowed)
// ---------------------------------------------------------------------------
__device__ __half g_Xh[MTOT*DIN];            // x in fp16
__device__ __half g_Wth[4][DIN*DOUT];        // W^T [n][k] fp16 (q,k,v,out)
__device__ __half g_Qh[MTOT*DOUT];
__device__ __half g_Kh[MTOT*DOUT];
__device__ __half g_Vth[BATCH*NH*HD*SEQ];    // V transposed [b,h,d,s]
__device__ __half g_Ah[MTOT*DOUT];           // attention output

// ---------------------------------------------------------------------------
// helpers
// ---------------------------------------------------------------------------
__device__ __forceinline__ uint32_t smem_u32(const void* p) {
    return (uint32_t)__cvta_generic_to_shared(p);
}

__device__ __forceinline__ void cp_async16(uint32_t dst, const void* src) {
    asm volatile("cp.async.cg.shared.global [%0], [%1], 16;" :: "r"(dst), "l"(src) : "memory");
}
__device__ __forceinline__ void cp_commit() {
    asm volatile("cp.async.commit_group;" ::: "memory");
}
__device__ __forceinline__ void cp_wait1() {
    asm volatile("cp.async.wait_group 1;" ::: "memory");
}

// m16n8k16 fp16 HMMA, row.col, fp32 accumulate
__device__ __forceinline__ void mma_f16(float* d, const uint32_t* a, const uint32_t* b) {
    asm volatile(
        "mma.sync.aligned.m16n8k16.row.col.f32.f16.f16.f32 "
        "{%0,%1,%2,%3}, {%4,%5,%6,%7}, {%8,%9}, {%0,%1,%2,%3};"
        : "+f"(d[0]), "+f"(d[1]), "+f"(d[2]), "+f"(d[3])
        : "r"(a[0]), "r"(a[1]), "r"(a[2]), "r"(a[3]), "r"(b[0]), "r"(b[1]));
}

// ---------------------------------------------------------------------------
// prep kernels
// ---------------------------------------------------------------------------
__global__ void x2h_kernel(const float* __restrict__ x) {
    int i = blockIdx.x * 256 + threadIdx.x;     // 1M float4
    float4 v = ((const float4*)x)[i];
    __half2 h0 = __floats2half2_rn(v.x, v.y);
    __half2 h1 = __floats2half2_rn(v.z, v.w);
    uint2 u;
    u.x = *(uint32_t*)&h0;
    u.y = *(uint32_t*)&h1;
    ((uint2*)g_Xh)[i] = u;
}

// transpose + convert: g_Wth[z][n*1024+k] = h(W[k*1024+n])
__global__ void wtrans_kernel(const float* __restrict__ Wq,
                              const float* __restrict__ Wk,
                              const float* __restrict__ Wv,
                              const float* __restrict__ Wo) {
    __shared__ float t[32][33];
    const float* W = (blockIdx.z == 0) ? Wq : (blockIdx.z == 1) ? Wk
                   : (blockIdx.z == 2) ? Wv : Wo;
    __half* out = g_Wth[blockIdx.z];
    int n0 = blockIdx.x * 32, k0 = blockIdx.y * 32;
    int tx = threadIdx.x, ty = threadIdx.y;   // 32 x 8
    #pragma unroll
    for (int i = 0; i < 4; i++)
        t[ty + 8*i][tx] = W[(size_t)(k0 + ty + 8*i) * DOUT + n0 + tx];
    __syncthreads();
    #pragma unroll
    for (int i = 0; i < 4; i++)
        out[(size_t)(n0 + ty + 8*i) * DIN + k0 + tx] = __float2half_rn(t[tx][ty + 8*i]);
}

// ---------------------------------------------------------------------------
// fp16 HMMA GEMM: C = A[M,1024] @ Bt[N,1024]^T, 128x128 CTA tile, 256 threads.
// 8 warps = 4(m) x 2(n), warp tile 32x64. BK=64, double-buffered cp.async.
// smem rows padded to 72 halves (bank-conflict-free fragments).
// EPI: 0 = fp32 store, 1 = fp16 store, 2 = fp16 V-transposed store
// ---------------------------------------------------------------------------
#define HST 72
#define STG_HALVES (128*HST)
#define GEMM_SMEM  (2*2*STG_HALVES*2)     // 73728 bytes

__device__ __forceinline__ void g_load_stage(const __half* __restrict__ A,
                                             const __half* __restrict__ Bt,
                                             uint32_t sA, uint32_t sB,
                                             int stage, int kc, int bm, int bn, int tid) {
    const __half* srcA = A  + (size_t)bm * DIN + kc * 64;
    const __half* srcB = Bt + (size_t)bn * DIN + kc * 64;
    const uint32_t dA = sA + stage * STG_HALVES * 2;
    const uint32_t dB = sB + stage * STG_HALVES * 2;
    #pragma unroll
    for (int i = 0; i < 4; i++) {
        int idx = tid + i * 256;        // 0..1023 = 128 rows x 8 chunks
        int row = idx >> 3, c8 = idx & 7;
        uint32_t off = (row * HST + c8 * 8) * 2;
        cp_async16(dA + off, srcA + (size_t)row * DIN + c8 * 8);
        cp_async16(dB + off, srcB + (size_t)row * DIN + c8 * 8);
    }
}

template<int EPI>
__device__ __forceinline__ void gemm_tile_body(const __half* __restrict__ A,
                                               const __half* __restrict__ Bt,
                                               void* __restrict__ Cv) {
    extern __shared__ __half hsmem[];
    __half* sA = hsmem;                       // [2][128][72]
    __half* sB = hsmem + 2 * STG_HALVES;      // [2][128][72]
    const uint32_t sAu = smem_u32(sA);
    const uint32_t sBu = smem_u32(sB);

    const int tid  = threadIdx.x;
    const int lane = tid & 31;
    const int wid  = tid >> 5;
    const int wm   = wid >> 1;              // 0..3
    const int wn   = wid & 1;               // 0..1
    const int bm   = blockIdx.y * 128;
    const int bn   = blockIdx.x * 128;
    const int gr   = lane >> 2;             // 0..7
    const int c2   = (lane & 3) * 2;        // 0,2,4,6

    float acc[16][4] = {};                  // [i*8+j][reg]

    const int NKC = DIN / 64;               // 16 chunks

    g_load_stage(A, Bt, sAu, sBu, 0, 0, bm, bn, tid);
    cp_commit();

    for (int kc = 0; kc < NKC; kc++) {
        if (kc + 1 < NKC)
            g_load_stage(A, Bt, sAu, sBu, (kc + 1) & 1, kc + 1, bm, bn, tid);
        cp_commit();
        cp_wait1();
        __syncthreads();

        const __half* cA = sA + (kc & 1) * STG_HALVES;
        const __half* cB = sB + (kc & 1) * STG_HALVES;

        #pragma unroll
        for (int ks = 0; ks < 4; ks++) {
            const int k0 = ks * 16;
            uint32_t a[2][4];
            #pragma unroll
            for (int i = 0; i < 2; i++) {
                const __half* ab = cA + (wm * 32 + i * 16 + gr) * HST + k0 + c2;
                a[i][0] = *(const uint32_t*)(ab);
                a[i][1] = *(const uint32_t*)(ab + 8 * HST);
                a[i][2] = *(const uint32_t*)(ab + 8);
                a[i][3] = *(const uint32_t*)(ab + 8 * HST + 8);
            }
            #pragma unroll
            for (int j = 0; j < 8; j++) {
                const __half* bb = cB + (wn * 64 + j * 8 + gr) * HST + k0 + c2;
                uint32_t b[2] = { *(const uint32_t*)(bb), *(const uint32_t*)(bb + 8) };
                mma_f16(acc[j],     a[0], b);
                mma_f16(acc[8 + j], a[1], b);
            }
        }
        __syncthreads();
    }

    // epilogue: c0:(gr, c2) c1:(gr, c2+1) c2:(gr+8, c2) c3:(gr+8, c2+1)
    #pragma unroll
    for (int i = 0; i < 2; i++) {
        const int row = bm + wm * 32 + i * 16 + gr;
        #pragma unroll
        for (int j = 0; j < 8; j++) {
            const int col = bn + wn * 64 + j * 8 + c2;
            float v0 = acc[i*8+j][0], v1 = acc[i*8+j][1];
            float v2 = acc[i*8+j][2], v3 = acc[i*8+j][3];
            if (EPI == 0) {
                float* C = (float*)Cv;
                *(float2*)(C + (size_t)row * DOUT + col)       = make_float2(v0, v1);
                *(float2*)(C + (size_t)(row + 8) * DOUT + col) = make_float2(v2, v3);
            } else if (EPI == 1) {
                __half* C = (__half*)Cv;
                __half2 h0 = __floats2half2_rn(v0, v1);
                __half2 h1 = __floats2half2_rn(v2, v3);
                *(__half2*)(C + (size_t)row * DOUT + col)       = h0;
                *(__half2*)(C + (size_t)(row + 8) * DOUT + col) = h1;
            } else {
                // g_Vth[((b*NH+h)*HD + d)*SEQ + s]; h=col>>6, d=col&63
                __half* C = (__half*)Cv;
                const int b0i = row >> 11,    s0 = row & 2047;
                const int b1i = (row+8) >> 11, s1 = (row+8) & 2047;
                #pragma unroll
                for (int q = 0; q < 2; q++) {
                    const int cc = col + q;
                    const size_t base = ((size_t)(cc >> 6) * HD + (cc & 63)) * SEQ;
                    C[(size_t)b0i * NH * HD * SEQ + base + s0] = __float2half_rn(q ? v1 : v0);
                    C[(size_t)b1i * NH * HD * SEQ + base + s1] = __float2half_rn(q ? v3 : v2);
                }
            }
        }
    }
}

__global__ void __launch_bounds__(256) qkv_mma_kernel() {
    if (blockIdx.z == 0)      gemm_tile_body<1>(g_Xh, g_Wth[0], g_Qh);
    else if (blockIdx.z == 1) gemm_tile_body<1>(g_Xh, g_Wth[1], g_Kh);
    else                      gemm_tile_body<2>(g_Xh, g_Wth[2], g_Vth);
}

__global__ void __launch_bounds__(256) out_mma_kernel(float* __restrict__ out) {
    gemm_tile_body<0>(g_Ah, g_Wth[3], out);
}

// ---------------------------------------------------------------------------
// fp16 tensor-core causal flash attention.
// grid (16 qtiles reversed, NH, BATCH), 256 threads = 8 warps x 16 rows.
// Key blocks of 64, cp.async double-buffered K/V. Q fragments in registers.
// smem: sK[2][64][72] sV[2][64][72] sP[128][72] halves = 54KB.
// ---------------------------------------------------------------------------
#define KBUF (64*HST)                    // halves per K/V buffer
#define ATTN_SMEM ((2*KBUF + 2*KBUF + 128*HST) * 2)   // 55296 bytes

__device__ __forceinline__ void attn_load(const __half* __restrict__ Kg,
                                          const __half* __restrict__ Vt,
                                          uint32_t sKu, uint32_t sVu,
                                          int buf, int kbase, int tid) {
    const uint32_t dK = sKu + buf * KBUF * 2;
    const uint32_t dV = sVu + buf * KBUF * 2;
    #pragma unroll
    for (int i = 0; i < 2; i++) {
        int idx = tid + i * 256;         // 0..511 = 64 rows x 8 chunks
        int row = idx >> 3, c8 = idx & 7;
        uint32_t off = (row * HST + c8 * 8) * 2;
        cp_async16(dK + off, Kg + (size_t)(kbase + row) * DOUT + c8 * 8);
        cp_async16(dV + off, Vt + (size_t)row * SEQ + kbase + c8 * 8);
    }
}

__global__ void __launch_bounds__(256, 2) attn_f16_kernel() {
    extern __shared__ __half hsmem[];
    __half* sK = hsmem;                  // [2][64][72]
    __half* sV = sK + 2 * KBUF;          // [2][64][72]
    __half* sP = sV + 2 * KBUF;          // [128][72]
    const uint32_t sKu = smem_u32(sK);
    const uint32_t sVu = smem_u32(sV);

    const int qt  = 15 - blockIdx.x;     // long CTAs first
    const int h   = blockIdx.y;
    const int b   = blockIdx.z;
    const int tid = threadIdx.x;
    const int lane = tid & 31;
    const int wid  = tid >> 5;
    const int gr = lane >> 2, c2 = (lane & 3) * 2;

    const int qbase = qt * 128;
    const size_t rowbase = (size_t)b * SEQ;
    const int colbase = h * HD;
    const __half* Kg = g_Kh + rowbase * DOUT + colbase;
    const __half* Vt = g_Vth + (size_t)(b * NH + h) * HD * SEQ;

    const int wrow = wid * 16;

    // preload Q fragments: rows wrow..wrow+15, k=0..63
    uint32_t qf[4][4];
    {
        const __half* Qg = g_Qh + (rowbase + qbase + wrow + gr) * DOUT + colbase + c2;
        #pragma unroll
        for (int ks = 0; ks < 4; ks++) {
            const __half* qp = Qg + ks * 16;
            qf[ks][0] = *(const uint32_t*)(qp);
            qf[ks][1] = *(const uint32_t*)(qp + 8 * DOUT);
            qf[ks][2] = *(const uint32_t*)(qp + 8);
            qf[ks][3] = *(const uint32_t*)(qp + 8 * DOUT + 8);
        }
    }

    float o[8][4] = {};
    float m0 = -1e30f, m1 = -1e30f, l0 = 0.f, l1 = 0.f;
    const int qg0 = qbase + wrow + gr;
    const int qg1 = qg0 + 8;
    const unsigned FULL = 0xffffffffu;

    const int nkb = 2 * qt + 2;

    attn_load(Kg, Vt, sKu, sVu, 0, 0, tid);
    cp_commit();

    for (int kb = 0; kb < nkb; kb++) {
        __syncthreads();                 // buffer (kb+1)&1 free for reuse
        if (kb + 1 < nkb)
            attn_load(Kg, Vt, sKu, sVu, (kb + 1) & 1, (kb + 1) * 64, tid);
        cp_commit();
        cp_wait1();                      // block kb resident
        __syncthreads();

        const __half* cK = sK + (kb & 1) * KBUF;
        const __half* cV = sV + (kb & 1) * KBUF;
        const int kbase = kb * 64;

        // S = Q K^T
        float s[8][4] = {};
        #pragma unroll
        for (int ks = 0; ks < 4; ks++) {
            #pragma unroll
            for (int j = 0; j < 8; j++) {
                const __half* bp = cK + (j * 8 + gr) * HST + ks * 16 + c2;
                uint32_t bf[2] = { *(const uint32_t*)(bp), *(const uint32_t*)(bp + 8) };
                mma_f16(s[j], qf[ks], bf);
            }
        }

        // scale + causal mask + row max
        float rx0 = -1e30f, rx1 = -1e30f;
        #pragma unroll
        for (int j = 0; j < 8; j++) {
            int col0 = kbase + j * 8 + c2;
            s[j][0] = (col0     <= qg0) ? s[j][0] * 0.125f : -1e30f;
            s[j][1] = (col0 + 1 <= qg0) ? s[j][1] * 0.125f : -1e30f;
            s[j][2] = (col0     <= qg1) ? s[j][2] * 0.125f : -1e30f;
            s[j][3] = (col0 + 1 <= qg1) ? s[j][3] * 0.125f : -1e30f;
            rx0 = fmaxf(rx0, fmaxf(s[j][0], s[j][1]));
            rx1 = fmaxf(rx1, fmaxf(s[j][2], s[j][3]));
        }
        rx0 = fmaxf(rx0, __shfl_xor_sync(FULL, rx0, 1));
        rx0 = fmaxf(rx0, __shfl_xor_sync(FULL, rx0, 2));
        rx1 = fmaxf(rx1, __shfl_xor_sync(FULL, rx1, 1));
        rx1 = fmaxf(rx1, __shfl_xor_sync(FULL, rx1, 2));

        float nm0 = fmaxf(m0, rx0), nm1 = fmaxf(m1, rx1);
        float sum0 = 0.f, sum1 = 0.f;
        #pragma unroll
        for (int j = 0; j < 8; j++) {
            s[j][0] = __expf(s[j][0] - nm0);
            s[j][1] = __expf(s[j][1] - nm0);
            s[j][2] = __expf(s[j][2] - nm1);
            s[j][3] = __expf(s[j][3] - nm1);
            sum0 += s[j][0] + s[j][1];
            sum1 += s[j][2] + s[j][3];
        }
        sum0 += __shfl_xor_sync(FULL, sum0, 1);
        sum0 += __shfl_xor_sync(FULL, sum0, 2);
        sum1 += __shfl_xor_sync(FULL, sum1, 1);
        sum1 += __shfl_xor_sync(FULL, sum1, 2);

        float a0 = __expf(m0 - nm0), a1 = __expf(m1 - nm1);
        l0 = l0 * a0 + sum0;  l1 = l1 * a1 + sum1;
        m0 = nm0;  m1 = nm1;
        #pragma unroll
        for (int j = 0; j < 8; j++) {
            o[j][0] *= a0; o[j][1] *= a0;
            o[j][2] *= a1; o[j][3] *= a1;
        }

        // P -> fp16 smem (warp-private rows)
        #pragma unroll
        for (int j = 0; j < 8; j++) {
            *(__half2*)&sP[(wrow + gr) * HST + j * 8 + c2] =
                __floats2half2_rn(s[j][0], s[j][1]);
            *(__half2*)&sP[(wrow + gr + 8) * HST + j * 8 + c2] =
                __floats2half2_rn(s[j][2], s[j][3]);
        }
        __syncwarp();

        // O += P V  (B = Vt[dim][key] col-major over k=key)
        #pragma unroll
        for (int ks = 0; ks < 4; ks++) {
            const __half* ap = &sP[(wrow + gr) * HST + ks * 16 + c2];
            uint32_t a[4] = { *(const uint32_t*)(ap),
                              *(const uint32_t*)(ap + 8 * HST),
                              *(const uint32_t*)(ap + 8),
                              *(const uint32_t*)(ap + 8 * HST + 8) };
            #pragma unroll
            for (int j = 0; j < 8; j++) {
                const __half* bp = cV + (j * 8 + gr) * HST + ks * 16 + c2;
                uint32_t bf[2] = { *(const uint32_t*)(bp), *(const uint32_t*)(bp + 8) };
                mma_f16(o[j], a, bf);
            }
        }
    }

    // normalize + fp16 store
    const float inv0 = 1.f / l0, inv1 = 1.f / l1;
    #pragma unroll
    for (int j = 0; j < 8; j++) {
        const int col = colbase + j * 8 + c2;
        *(__half2*)&g_Ah[(rowbase + qbase + wrow + gr) * DOUT + col] =
            __floats2half2_rn(o[j][0] * inv0, o[j][1] * inv0);
        *(__half2*)&g_Ah[(rowbase + qbase + wrow + gr + 8) * DOUT + col] =
            __floats2half2_rn(o[j][2] * inv1, o[j][3] * inv1);
    }
}

// ---------------------------------------------------------------------------
extern "C" void kernel_launch(void* const* d_in, const int* in_sizes, int n_in,
                              void* d_out, int out_size) {
    (void)in_sizes; (void)n_in; (void)out_size;
    const float* x    = (const float*)d_in[0];
    const float* Wq   = (const float*)d_in[1];
    const float* Wk   = (const float*)d_in[2];
    const float* Wv   = (const float*)d_in[3];
    const float* Wout = (const float*)d_in[4];
    float* out = (float*)d_out;

    static bool attr_set = false;
    if (!attr_set) {
        cudaFuncSetAttribute(attn_f16_kernel,
                             cudaFuncAttributeMaxDynamicSharedMemorySize, ATTN_SMEM);
        cudaFuncSetAttribute(qkv_mma_kernel,
                             cudaFuncAttributeMaxDynamicSharedMemorySize, GEMM_SMEM);
        cudaFuncSetAttribute(out_mma_kernel,
                             cudaFuncAttributeMaxDynamicSharedMemorySize, GEMM_SMEM);
        attr_set = true;
    }

    x2h_kernel<<<(MTOT*DIN)/(256*4), 256>>>(x);
    wtrans_kernel<<<dim3(DOUT/32, DIN/32, 4), dim3(32, 8)>>>(Wq, Wk, Wv, Wout);

    qkv_mma_kernel<<<dim3(DOUT/128, MTOT/128, 3), 256, GEMM_SMEM>>>();

    attn_f16_kernel<<<dim3(SEQ/128, NH, BATCH), 256, ATTN_SMEM>>>();

    out_mma_kernel<<<dim3(DOUT/128, MTOT/128), 256, GEMM_SMEM>>>(out);
}

// round 6
// speedup vs baseline: 6.4959x; 1.1193x over previous
#include <cuda_runtime.h>
#include <cuda_fp16.h>
#include <math.h>
#include <stdint.h>

#define BATCH 2
#define SEQ   2048
#define DIN   1024
#define DOUT  1024
#define NH    16
#define HD    64
#define MTOT  (BATCH*SEQ)   // 4096

// ---------------------------------------------------------------------------
// scratch (no cudaMalloc allowed)
// ---------------------------------------------------------------------------
__device__ __half g_Xh[MTOT*DIN];            // x in fp16
__device__ __half g_Wth[4][DIN*DOUT];        // W^T [n][k] fp16 (q,k,v,out)
__device__ __half g_Qh[MTOT*DOUT];           // pre-scaled by 0.125*log2(e)
__device__ __half g_Kh[MTOT*DOUT];
__device__ __half g_Vth[BATCH*NH*HD*SEQ];    // V transposed [b,h,d,s]
__device__ __half g_Ah[MTOT*DOUT];           // attention output

// ---------------------------------------------------------------------------
// helpers
// ---------------------------------------------------------------------------
__device__ __forceinline__ uint32_t smem_u32(const void* p) {
    return (uint32_t)__cvta_generic_to_shared(p);
}

__device__ __forceinline__ void cp_async16(uint32_t dst, const void* src) {
    asm volatile("cp.async.cg.shared.global [%0], [%1], 16;" :: "r"(dst), "l"(src) : "memory");
}
__device__ __forceinline__ void cp_commit() {
    asm volatile("cp.async.commit_group;" ::: "memory");
}
__device__ __forceinline__ void cp_wait1() {
    asm volatile("cp.async.wait_group 1;" ::: "memory");
}

__device__ __forceinline__ float ex2(float x) {
    float y; asm("ex2.approx.f32 %0, %1;" : "=f"(y) : "f"(x)); return y;
}

// m16n8k16 fp16 HMMA, row.col, fp32 accumulate
__device__ __forceinline__ void mma_f16(float* d, const uint32_t* a, const uint32_t* b) {
    asm volatile(
        "mma.sync.aligned.m16n8k16.row.col.f32.f16.f16.f32 "
        "{%0,%1,%2,%3}, {%4,%5,%6,%7}, {%8,%9}, {%0,%1,%2,%3};"
        : "+f"(d[0]), "+f"(d[1]), "+f"(d[2]), "+f"(d[3])
        : "r"(a[0]), "r"(a[1]), "r"(a[2]), "r"(a[3]), "r"(b[0]), "r"(b[1]));
}

__device__ __forceinline__ void ldsm_x4(uint32_t* r, uint32_t addr) {
    asm volatile("ldmatrix.sync.aligned.m8n8.x4.shared.b16 {%0,%1,%2,%3}, [%4];"
        : "=r"(r[0]), "=r"(r[1]), "=r"(r[2]), "=r"(r[3]) : "r"(addr));
}

// ---------------------------------------------------------------------------
// prep kernels
// ---------------------------------------------------------------------------
__global__ void x2h_kernel(const float* __restrict__ x) {
    int i = blockIdx.x * 256 + threadIdx.x;     // 1M float4
    float4 v = ((const float4*)x)[i];
    __half2 h0 = __floats2half2_rn(v.x, v.y);
    __half2 h1 = __floats2half2_rn(v.z, v.w);
    uint2 u;
    u.x = *(uint32_t*)&h0;
    u.y = *(uint32_t*)&h1;
    ((uint2*)g_Xh)[i] = u;
}

// transpose + convert: g_Wth[z][n*1024+k] = h(W[k*1024+n])
__global__ void wtrans_kernel(const float* __restrict__ Wq,
                              const float* __restrict__ Wk,
                              const float* __restrict__ Wv,
                              const float* __restrict__ Wo) {
    __shared__ float t[32][33];
    const float* W = (blockIdx.z == 0) ? Wq : (blockIdx.z == 1) ? Wk
                   : (blockIdx.z == 2) ? Wv : Wo;
    __half* out = g_Wth[blockIdx.z];
    int n0 = blockIdx.x * 32, k0 = blockIdx.y * 32;
    int tx = threadIdx.x, ty = threadIdx.y;   // 32 x 8
    #pragma unroll
    for (int i = 0; i < 4; i++)
        t[ty + 8*i][tx] = W[(size_t)(k0 + ty + 8*i) * DOUT + n0 + tx];
    __syncthreads();
    #pragma unroll
    for (int i = 0; i < 4; i++)
        out[(size_t)(n0 + ty + 8*i) * DIN + k0 + tx] = __float2half_rn(t[tx][ty + 8*i]);
}

// ---------------------------------------------------------------------------
// fp16 HMMA GEMM: C = A[M,1024] @ Bt[N,1024]^T, 128x128 CTA tile, 256 threads.
// 8 warps = 4(m) x 2(n), warp tile 32x64. BK=64, double-buffered cp.async.
// ldmatrix.x4 fragment loads. EPI: 0=fp32, 1=fp16*scale, 2=fp16 V-transposed.
// ---------------------------------------------------------------------------
#define HST 72
#define STG_HALVES (128*HST)
#define GEMM_SMEM  (2*2*STG_HALVES*2)     // 73728 bytes

__device__ __forceinline__ void g_load_stage(const __half* __restrict__ A,
                                             const __half* __restrict__ Bt,
                                             uint32_t sA, uint32_t sB,
                                             int stage, int kc, int bm, int bn, int tid) {
    const __half* srcA = A  + (size_t)bm * DIN + kc * 64;
    const __half* srcB = Bt + (size_t)bn * DIN + kc * 64;
    const uint32_t dA = sA + stage * STG_HALVES * 2;
    const uint32_t dB = sB + stage * STG_HALVES * 2;
    #pragma unroll
    for (int i = 0; i < 4; i++) {
        int idx = tid + i * 256;        // 0..1023 = 128 rows x 8 chunks
        int row = idx >> 3, c8 = idx & 7;
        uint32_t off = (row * HST + c8 * 8) * 2;
        cp_async16(dA + off, srcA + (size_t)row * DIN + c8 * 8);
        cp_async16(dB + off, srcB + (size_t)row * DIN + c8 * 8);
    }
}

template<int EPI>
__device__ __forceinline__ void gemm_tile_body(const __half* __restrict__ A,
                                               const __half* __restrict__ Bt,
                                               void* __restrict__ Cv, float escale) {
    extern __shared__ __half hsmem[];
    const uint32_t sAu = smem_u32(hsmem);
    const uint32_t sBu = sAu + 2 * STG_HALVES * 2;

    const int tid  = threadIdx.x;
    const int lane = tid & 31;
    const int wid  = tid >> 5;
    const int wm   = wid >> 1;              // 0..3
    const int wn   = wid & 1;               // 0..1
    const int bm   = blockIdx.y * 128;
    const int bn   = blockIdx.x * 128;
    const int gr   = lane >> 2;             // 0..7
    const int c2   = (lane & 3) * 2;        // 0,2,4,6

    // ldmatrix lane address components
    const int lA_row = lane & 15;           // + (lane>>4)*8 k-offset
    const int lA_col = (lane >> 4) * 8;
    const int lB_row = (lane & 7) + ((lane >> 4) & 1) * 8;
    const int lB_col = ((lane >> 3) & 1) * 8;

    float acc[16][4] = {};                  // [i*8+j][reg]

    const int NKC = DIN / 64;               // 16 chunks

    g_load_stage(A, Bt, sAu, sBu, 0, 0, bm, bn, tid);
    cp_commit();

    for (int kc = 0; kc < NKC; kc++) {
        if (kc + 1 < NKC)
            g_load_stage(A, Bt, sAu, sBu, (kc + 1) & 1, kc + 1, bm, bn, tid);
        cp_commit();
        cp_wait1();
        __syncthreads();

        const uint32_t cA = sAu + (kc & 1) * STG_HALVES * 2;
        const uint32_t cB = sBu + (kc & 1) * STG_HALVES * 2;

        #pragma unroll
        for (int ks = 0; ks < 4; ks++) {
            const int k0 = ks * 16;
            uint32_t a[2][4];
            #pragma unroll
            for (int i = 0; i < 2; i++)
                ldsm_x4(a[i], cA + (((wm * 32 + i * 16 + lA_row) * HST + k0 + lA_col) << 1));
            uint32_t b[4][4];
            #pragma unroll
            for (int jj = 0; jj < 4; jj++)
                ldsm_x4(b[jj], cB + (((wn * 64 + jj * 16 + lB_row) * HST + k0 + lB_col) << 1));
            #pragma unroll
            for (int j = 0; j < 8; j++) {
                const uint32_t* bf = &b[j >> 1][(j & 1) * 2];
                mma_f16(acc[j],     a[0], bf);
                mma_f16(acc[8 + j], a[1], bf);
            }
        }
        __syncthreads();
    }

    // epilogue: c0:(gr, c2) c1:(gr, c2+1) c2:(gr+8, c2) c3:(gr+8, c2+1)
    #pragma unroll
    for (int i = 0; i < 2; i++) {
        const int row = bm + wm * 32 + i * 16 + gr;
        #pragma unroll
        for (int j = 0; j < 8; j++) {
            const int col = bn + wn * 64 + j * 8 + c2;
            float v0 = acc[i*8+j][0], v1 = acc[i*8+j][1];
            float v2 = acc[i*8+j][2], v3 = acc[i*8+j][3];
            if (EPI == 0) {
                float* C = (float*)Cv;
                *(float2*)(C + (size_t)row * DOUT + col)       = make_float2(v0, v1);
                *(float2*)(C + (size_t)(row + 8) * DOUT + col) = make_float2(v2, v3);
            } else if (EPI == 1) {
                __half* C = (__half*)Cv;
                *(__half2*)(C + (size_t)row * DOUT + col)       = __floats2half2_rn(v0*escale, v1*escale);
                *(__half2*)(C + (size_t)(row + 8) * DOUT + col) = __floats2half2_rn(v2*escale, v3*escale);
            } else {
                // g_Vth[((b*NH+h)*HD + d)*SEQ + s]; h=col>>6, d=col&63
                __half* C = (__half*)Cv;
                const int b0i = row >> 11,     s0 = row & 2047;
                const int b1i = (row+8) >> 11, s1 = (row+8) & 2047;
                #pragma unroll
                for (int q = 0; q < 2; q++) {
                    const int cc = col + q;
                    const size_t base = ((size_t)(cc >> 6) * HD + (cc & 63)) * SEQ;
                    C[(size_t)b0i * NH * HD * SEQ + base + s0] = __float2half_rn(q ? v1 : v0);
                    C[(size_t)b1i * NH * HD * SEQ + base + s1] = __float2half_rn(q ? v3 : v2);
                }
            }
        }
    }
}

#define QSCALE (0.125f * 1.4426950408889634f)   // 1/sqrt(64) * log2(e)

__global__ void __launch_bounds__(256) qkv_mma_kernel() {
    if (blockIdx.z == 0)      gemm_tile_body<1>(g_Xh, g_Wth[0], g_Qh, QSCALE);
    else if (blockIdx.z == 1) gemm_tile_body<1>(g_Xh, g_Wth[1], g_Kh, 1.0f);
    else                      gemm_tile_body<2>(g_Xh, g_Wth[2], g_Vth, 1.0f);
}

__global__ void __launch_bounds__(256) out_mma_kernel(float* __restrict__ out) {
    gemm_tile_body<0>(g_Ah, g_Wth[3], out, 1.0f);
}

// ---------------------------------------------------------------------------
// fp16 tensor-core causal flash attention (base-2 softmax, Q pre-scaled).
// grid (16 qtiles reversed, NH, BATCH), 256 threads = 8 warps x 16 rows.
// Key blocks of 64, cp.async double-buffered K/V, ldmatrix fragments.
// ---------------------------------------------------------------------------
#define KBUF (64*HST)                    // halves per K/V buffer
#define ATTN_SMEM ((2*KBUF + 2*KBUF + 128*HST) * 2)   // 55296 bytes

__device__ __forceinline__ void attn_load(const __half* __restrict__ Kg,
                                          const __half* __restrict__ Vt,
                                          uint32_t sKu, uint32_t sVu,
                                          int buf, int kbase, int tid) {
    const uint32_t dK = sKu + buf * KBUF * 2;
    const uint32_t dV = sVu + buf * KBUF * 2;
    #pragma unroll
    for (int i = 0; i < 2; i++) {
        int idx = tid + i * 256;         // 0..511 = 64 rows x 8 chunks
        int row = idx >> 3, c8 = idx & 7;
        uint32_t off = (row * HST + c8 * 8) * 2;
        cp_async16(dK + off, Kg + (size_t)(kbase + row) * DOUT + c8 * 8);
        cp_async16(dV + off, Vt + (size_t)row * SEQ + kbase + c8 * 8);
    }
}

__global__ void __launch_bounds__(256, 2) attn_f16_kernel() {
    extern __shared__ __half hsmem[];
    const uint32_t sKu = smem_u32(hsmem);
    const uint32_t sVu = sKu + 2 * KBUF * 2;
    const uint32_t sPu = sVu + 2 * KBUF * 2;
    __half* sP = hsmem + 4 * KBUF;

    const int qt  = 15 - blockIdx.x;     // long CTAs first
    const int h   = blockIdx.y;
    const int b   = blockIdx.z;
    const int tid = threadIdx.x;
    const int lane = tid & 31;
    const int wid  = tid >> 5;
    const int gr = lane >> 2, c2 = (lane & 3) * 2;

    const int lA_row = lane & 15;
    const int lA_col = (lane >> 4) * 8;
    const int lB_row = (lane & 7) + ((lane >> 4) & 1) * 8;
    const int lB_col = ((lane >> 3) & 1) * 8;

    const int qbase = qt * 128;
    const size_t rowbase = (size_t)b * SEQ;
    const int colbase = h * HD;
    const __half* Kg = g_Kh + rowbase * DOUT + colbase;
    const __half* Vt = g_Vth + (size_t)(b * NH + h) * HD * SEQ;

    const int wrow = wid * 16;

    // preload Q fragments (already scaled by 0.125*log2e)
    uint32_t qf[4][4];
    {
        const __half* Qg = g_Qh + (rowbase + qbase + wrow + gr) * DOUT + colbase + c2;
        #pragma unroll
        for (int ks = 0; ks < 4; ks++) {
            const __half* qp = Qg + ks * 16;
            qf[ks][0] = *(const uint32_t*)(qp);
            qf[ks][1] = *(const uint32_t*)(qp + 8 * DOUT);
            qf[ks][2] = *(const uint32_t*)(qp + 8);
            qf[ks][3] = *(const uint32_t*)(qp + 8 * DOUT + 8);
        }
    }

    float o[8][4] = {};
    float m0 = -1e30f, m1 = -1e30f, l0 = 0.f, l1 = 0.f;
    const int qg0 = qbase + wrow + gr;
    const int qg1 = qg0 + 8;
    const unsigned FULL = 0xffffffffu;

    const int nkb = 2 * qt + 2;

    attn_load(Kg, Vt, sKu, sVu, 0, 0, tid);
    cp_commit();

    for (int kb = 0; kb < nkb; kb++) {
        __syncthreads();                 // buffer (kb+1)&1 free for reuse
        if (kb + 1 < nkb)
            attn_load(Kg, Vt, sKu, sVu, (kb + 1) & 1, (kb + 1) * 64, tid);
        cp_commit();
        cp_wait1();                      // block kb resident
        __syncthreads();

        const uint32_t cK = sKu + (kb & 1) * KBUF * 2;
        const uint32_t cV = sVu + (kb & 1) * KBUF * 2;
        const int kbase = kb * 64;

        // S = Q K^T  (S already in base-2 log scale: Q pre-scaled)
        float s[8][4] = {};
        #pragma unroll
        for (int ks = 0; ks < 4; ks++) {
            const int k0 = ks * 16;
            uint32_t bk[4][4];
            #pragma unroll
            for (int jj = 0; jj < 4; jj++)
                ldsm_x4(bk[jj], cK + (((jj * 16 + lB_row) * HST + k0 + lB_col) << 1));
            #pragma unroll
            for (int j = 0; j < 8; j++)
                mma_f16(s[j], qf[ks], &bk[j >> 1][(j & 1) * 2]);
        }

        // causal mask only when this warp's rows intersect the block diagonal
        if (kbase + 63 > qbase + wrow) {
            #pragma unroll
            for (int j = 0; j < 8; j++) {
                const int col0 = kbase + j * 8 + c2;
                if (col0     > qg0) s[j][0] = -1e30f;
                if (col0 + 1 > qg0) s[j][1] = -1e30f;
                if (col0     > qg1) s[j][2] = -1e30f;
                if (col0 + 1 > qg1) s[j][3] = -1e30f;
            }
        }

        // row max
        float rx0 = -1e30f, rx1 = -1e30f;
        #pragma unroll
        for (int j = 0; j < 8; j++) {
            rx0 = fmaxf(rx0, fmaxf(s[j][0], s[j][1]));
            rx1 = fmaxf(rx1, fmaxf(s[j][2], s[j][3]));
        }
        rx0 = fmaxf(rx0, __shfl_xor_sync(FULL, rx0, 1));
        rx0 = fmaxf(rx0, __shfl_xor_sync(FULL, rx0, 2));
        rx1 = fmaxf(rx1, __shfl_xor_sync(FULL, rx1, 1));
        rx1 = fmaxf(rx1, __shfl_xor_sync(FULL, rx1, 2));

        float nm0 = fmaxf(m0, rx0), nm1 = fmaxf(m1, rx1);
        float sum0 = 0.f, sum1 = 0.f;
        #pragma unroll
        for (int j = 0; j < 8; j++) {
            s[j][0] = ex2(s[j][0] - nm0);
            s[j][1] = ex2(s[j][1] - nm0);
            s[j][2] = ex2(s[j][2] - nm1);
            s[j][3] = ex2(s[j][3] - nm1);
            sum0 += s[j][0] + s[j][1];
            sum1 += s[j][2] + s[j][3];
        }
        sum0 += __shfl_xor_sync(FULL, sum0, 1);
        sum0 += __shfl_xor_sync(FULL, sum0, 2);
        sum1 += __shfl_xor_sync(FULL, sum1, 1);
        sum1 += __shfl_xor_sync(FULL, sum1, 2);

        float a0 = ex2(m0 - nm0), a1 = ex2(m1 - nm1);
        l0 = l0 * a0 + sum0;  l1 = l1 * a1 + sum1;
        m0 = nm0;  m1 = nm1;
        #pragma unroll
        for (int j = 0; j < 8; j++) {
            o[j][0] *= a0; o[j][1] *= a0;
            o[j][2] *= a1; o[j][3] *= a1;
        }

        // P -> fp16 smem (warp-private rows)
        #pragma unroll
        for (int j = 0; j < 8; j++) {
            *(__half2*)&sP[(wrow + gr) * HST + j * 8 + c2] =
                __floats2half2_rn(s[j][0], s[j][1]);
            *(__half2*)&sP[(wrow + gr + 8) * HST + j * 8 + c2] =
                __floats2half2_rn(s[j][2], s[j][3]);
        }
        __syncwarp();

        // O += P V
        #pragma unroll
        for (int ks = 0; ks < 4; ks++) {
            const int k0 = ks * 16;
            uint32_t ap[4];
            ldsm_x4(ap, sPu + (((wrow + lA_row) * HST + k0 + lA_col) << 1));
            uint32_t bv[4][4];
            #pragma unroll
            for (int jj = 0; jj < 4; jj++)
                ldsm_x4(bv[jj], cV + (((jj * 16 + lB_row) * HST + k0 + lB_col) << 1));
            #pragma unroll
            for (int j = 0; j < 8; j++)
                mma_f16(o[j], ap, &bv[j >> 1][(j & 1) * 2]);
        }
    }

    // normalize + fp16 store
    const float inv0 = 1.f / l0, inv1 = 1.f / l1;
    #pragma unroll
    for (int j = 0; j < 8; j++) {
        const int col = colbase + j * 8 + c2;
        *(__half2*)&g_Ah[(rowbase + qbase + wrow + gr) * DOUT + col] =
            __floats2half2_rn(o[j][0] * inv0, o[j][1] * inv0);
        *(__half2*)&g_Ah[(rowbase + qbase + wrow + gr + 8) * DOUT + col] =
            __floats2half2_rn(o[j][2] * inv1, o[j][3] * inv1);
    }
}

// ---------------------------------------------------------------------------
extern "C" void kernel_launch(void* const* d_in, const int* in_sizes, int n_in,
                              void* d_out, int out_size) {
    (void)in_sizes; (void)n_in; (void)out_size;
    const float* x    = (const float*)d_in[0];
    const float* Wq   = (const float*)d_in[1];
    const float* Wk   = (const float*)d_in[2];
    const float* Wv   = (const float*)d_in[3];
    const float* Wout = (const float*)d_in[4];
    float* out = (float*)d_out;

    static bool attr_set = false;
    if (!attr_set) {
        cudaFuncSetAttribute(attn_f16_kernel,
                             cudaFuncAttributeMaxDynamicSharedMemorySize, ATTN_SMEM);
        cudaFuncSetAttribute(qkv_mma_kernel,
                             cudaFuncAttributeMaxDynamicSharedMemorySize, GEMM_SMEM);
        cudaFuncSetAttribute(out_mma_kernel,
                             cudaFuncAttributeMaxDynamicSharedMemorySize, GEMM_SMEM);
        attr_set = true;
    }

    x2h_kernel<<<(MTOT*DIN)/(256*4), 256>>>(x);
    wtrans_kernel<<<dim3(DOUT/32, DIN/32, 4), dim3(32, 8)>>>(Wq, Wk, Wv, Wout);

    qkv_mma_kernel<<<dim3(DOUT/128, MTOT/128, 3), 256, GEMM_SMEM>>>();

    attn_f16_kernel<<<dim3(SEQ/128, NH, BATCH), 256, ATTN_SMEM>>>();

    out_mma_kernel<<<dim3(DOUT/128, MTOT/128), 256, GEMM_SMEM>>>(out);
}

// round 7
// speedup vs baseline: 7.2615x; 1.1179x over previous
#include <cuda_runtime.h>
#include <cuda_fp16.h>
#include <math.h>
#include <stdint.h>

#define BATCH 2
#define SEQ   2048
#define DIN   1024
#define DOUT  1024
#define NH    16
#define HD    64
#define MTOT  (BATCH*SEQ)   // 4096

// ---------------------------------------------------------------------------
// scratch (no cudaMalloc allowed)
// ---------------------------------------------------------------------------
__device__ __half g_Xh[MTOT*DIN];            // x in fp16
__device__ __half g_Wth[4][DIN*DOUT];        // W^T [n][k] fp16 (q,k,v,out)
__device__ __half g_Qh[MTOT*DOUT];           // pre-scaled by 0.125*log2(e)
__device__ __half g_Kh[MTOT*DOUT];
__device__ __half g_Vth[BATCH*NH*HD*SEQ];    // V transposed [b,h,d,s]
__device__ __half g_Ah[MTOT*DOUT];           // attention output

// ---------------------------------------------------------------------------
// helpers
// ---------------------------------------------------------------------------
__device__ __forceinline__ uint32_t smem_u32(const void* p) {
    return (uint32_t)__cvta_generic_to_shared(p);
}

__device__ __forceinline__ void cp_async16(uint32_t dst, const void* src) {
    asm volatile("cp.async.cg.shared.global [%0], [%1], 16;" :: "r"(dst), "l"(src) : "memory");
}
__device__ __forceinline__ void cp_commit() {
    asm volatile("cp.async.commit_group;" ::: "memory");
}
__device__ __forceinline__ void cp_wait1() {
    asm volatile("cp.async.wait_group 1;" ::: "memory");
}

__device__ __forceinline__ float ex2(float x) {
    float y; asm("ex2.approx.f32 %0, %1;" : "=f"(y) : "f"(x)); return y;
}

__device__ __forceinline__ uint32_t packh2(float a, float b) {
    __half2 h = __floats2half2_rn(a, b);
    return *(uint32_t*)&h;
}

// m16n8k16 fp16 HMMA, row.col, fp32 accumulate
__device__ __forceinline__ void mma_f16(float* d, const uint32_t* a, const uint32_t* b) {
    asm volatile(
        "mma.sync.aligned.m16n8k16.row.col.f32.f16.f16.f32 "
        "{%0,%1,%2,%3}, {%4,%5,%6,%7}, {%8,%9}, {%0,%1,%2,%3};"
        : "+f"(d[0]), "+f"(d[1]), "+f"(d[2]), "+f"(d[3])
        : "r"(a[0]), "r"(a[1]), "r"(a[2]), "r"(a[3]), "r"(b[0]), "r"(b[1]));
}

__device__ __forceinline__ void ldsm_x4(uint32_t* r, uint32_t addr) {
    asm volatile("ldmatrix.sync.aligned.m8n8.x4.shared.b16 {%0,%1,%2,%3}, [%4];"
        : "=r"(r[0]), "=r"(r[1]), "=r"(r[2]), "=r"(r[3]) : "r"(addr));
}

// ---------------------------------------------------------------------------
// prep kernels
// ---------------------------------------------------------------------------
__global__ void x2h_kernel(const float* __restrict__ x) {
    int i = blockIdx.x * 256 + threadIdx.x;     // 1M float4
    float4 v = ((const float4*)x)[i];
    __half2 h0 = __floats2half2_rn(v.x, v.y);
    __half2 h1 = __floats2half2_rn(v.z, v.w);
    uint2 u;
    u.x = *(uint32_t*)&h0;
    u.y = *(uint32_t*)&h1;
    ((uint2*)g_Xh)[i] = u;
}

// transpose + convert: g_Wth[z][n*1024+k] = h(W[k*1024+n])
__global__ void wtrans_kernel(const float* __restrict__ Wq,
                              const float* __restrict__ Wk,
                              const float* __restrict__ Wv,
                              const float* __restrict__ Wo) {
    __shared__ float t[32][33];
    const float* W = (blockIdx.z == 0) ? Wq : (blockIdx.z == 1) ? Wk
                   : (blockIdx.z == 2) ? Wv : Wo;
    __half* out = g_Wth[blockIdx.z];
    int n0 = blockIdx.x * 32, k0 = blockIdx.y * 32;
    int tx = threadIdx.x, ty = threadIdx.y;   // 32 x 8
    #pragma unroll
    for (int i = 0; i < 4; i++)
        t[ty + 8*i][tx] = W[(size_t)(k0 + ty + 8*i) * DOUT + n0 + tx];
    __syncthreads();
    #pragma unroll
    for (int i = 0; i < 4; i++)
        out[(size_t)(n0 + ty + 8*i) * DIN + k0 + tx] = __float2half_rn(t[tx][ty + 8*i]);
}

// ---------------------------------------------------------------------------
// fp16 HMMA GEMM: C = A[M,1024] @ Bt[N,1024]^T, 128x128 CTA tile, 256 threads.
// 8 warps = 4(m) x 2(n), warp tile 32x64. BK=64, double-buffered cp.async.
// ldmatrix.x4 fragment loads. EPI: 0=fp32, 1=fp16*scale, 2=fp16 V-transposed.
// ---------------------------------------------------------------------------
#define HST 72
#define STG_HALVES (128*HST)
#define GEMM_SMEM  (2*2*STG_HALVES*2)     // 73728 bytes

__device__ __forceinline__ void g_load_stage(const __half* __restrict__ A,
                                             const __half* __restrict__ Bt,
                                             uint32_t sA, uint32_t sB,
                                             int stage, int kc, int bm, int bn, int tid) {
    const __half* srcA = A  + (size_t)bm * DIN + kc * 64;
    const __half* srcB = Bt + (size_t)bn * DIN + kc * 64;
    const uint32_t dA = sA + stage * STG_HALVES * 2;
    const uint32_t dB = sB + stage * STG_HALVES * 2;
    #pragma unroll
    for (int i = 0; i < 4; i++) {
        int idx = tid + i * 256;        // 0..1023 = 128 rows x 8 chunks
        int row = idx >> 3, c8 = idx & 7;
        uint32_t off = (row * HST + c8 * 8) * 2;
        cp_async16(dA + off, srcA + (size_t)row * DIN + c8 * 8);
        cp_async16(dB + off, srcB + (size_t)row * DIN + c8 * 8);
    }
}

template<int EPI>
__device__ __forceinline__ void gemm_tile_body(const __half* __restrict__ A,
                                               const __half* __restrict__ Bt,
                                               void* __restrict__ Cv, float escale) {
    extern __shared__ __half hsmem[];
    const uint32_t sAu = smem_u32(hsmem);
    const uint32_t sBu = sAu + 2 * STG_HALVES * 2;

    const int tid  = threadIdx.x;
    const int lane = tid & 31;
    const int wid  = tid >> 5;
    const int wm   = wid >> 1;              // 0..3
    const int wn   = wid & 1;               // 0..1
    const int bm   = blockIdx.y * 128;
    const int bn   = blockIdx.x * 128;
    const int gr   = lane >> 2;             // 0..7
    const int c2   = (lane & 3) * 2;        // 0,2,4,6

    // ldmatrix lane address components
    const int lA_row = lane & 15;           // + (lane>>4)*8 k-offset
    const int lA_col = (lane >> 4) * 8;
    const int lB_row = (lane & 7) + ((lane >> 4) & 1) * 8;
    const int lB_col = ((lane >> 3) & 1) * 8;

    float acc[16][4] = {};                  // [i*8+j][reg]

    const int NKC = DIN / 64;               // 16 chunks

    g_load_stage(A, Bt, sAu, sBu, 0, 0, bm, bn, tid);
    cp_commit();

    for (int kc = 0; kc < NKC; kc++) {
        if (kc + 1 < NKC)
            g_load_stage(A, Bt, sAu, sBu, (kc + 1) & 1, kc + 1, bm, bn, tid);
        cp_commit();
        cp_wait1();
        __syncthreads();

        const uint32_t cA = sAu + (kc & 1) * STG_HALVES * 2;
        const uint32_t cB = sBu + (kc & 1) * STG_HALVES * 2;

        #pragma unroll
        for (int ks = 0; ks < 4; ks++) {
            const int k0 = ks * 16;
            uint32_t a[2][4];
            #pragma unroll
            for (int i = 0; i < 2; i++)
                ldsm_x4(a[i], cA + (((wm * 32 + i * 16 + lA_row) * HST + k0 + lA_col) << 1));
            uint32_t b[4][4];
            #pragma unroll
            for (int jj = 0; jj < 4; jj++)
                ldsm_x4(b[jj], cB + (((wn * 64 + jj * 16 + lB_row) * HST + k0 + lB_col) << 1));
            #pragma unroll
            for (int j = 0; j < 8; j++) {
                const uint32_t* bf = &b[j >> 1][(j & 1) * 2];
                mma_f16(acc[j],     a[0], bf);
                mma_f16(acc[8 + j], a[1], bf);
            }
        }
        __syncthreads();
    }

    // epilogue: c0:(gr, c2) c1:(gr, c2+1) c2:(gr+8, c2) c3:(gr+8, c2+1)
    #pragma unroll
    for (int i = 0; i < 2; i++) {
        const int row = bm + wm * 32 + i * 16 + gr;
        #pragma unroll
        for (int j = 0; j < 8; j++) {
            const int col = bn + wn * 64 + j * 8 + c2;
            float v0 = acc[i*8+j][0], v1 = acc[i*8+j][1];
            float v2 = acc[i*8+j][2], v3 = acc[i*8+j][3];
            if (EPI == 0) {
                float* C = (float*)Cv;
                *(float2*)(C + (size_t)row * DOUT + col)       = make_float2(v0, v1);
                *(float2*)(C + (size_t)(row + 8) * DOUT + col) = make_float2(v2, v3);
            } else if (EPI == 1) {
                __half* C = (__half*)Cv;
                *(__half2*)(C + (size_t)row * DOUT + col)       = __floats2half2_rn(v0*escale, v1*escale);
                *(__half2*)(C + (size_t)(row + 8) * DOUT + col) = __floats2half2_rn(v2*escale, v3*escale);
            } else {
                // g_Vth[((b*NH+h)*HD + d)*SEQ + s]; h=col>>6, d=col&63
                __half* C = (__half*)Cv;
                const int b0i = row >> 11,     s0 = row & 2047;
                const int b1i = (row+8) >> 11, s1 = (row+8) & 2047;
                #pragma unroll
                for (int q = 0; q < 2; q++) {
                    const int cc = col + q;
                    const size_t base = ((size_t)(cc >> 6) * HD + (cc & 63)) * SEQ;
                    C[(size_t)b0i * NH * HD * SEQ + base + s0] = __float2half_rn(q ? v1 : v0);
                    C[(size_t)b1i * NH * HD * SEQ + base + s1] = __float2half_rn(q ? v3 : v2);
                }
            }
        }
    }
}

#define QSCALE (0.125f * 1.4426950408889634f)   // 1/sqrt(64) * log2(e)

__global__ void __launch_bounds__(256) qkv_mma_kernel() {
    if (blockIdx.z == 0)      gemm_tile_body<1>(g_Xh, g_Wth[0], g_Qh, QSCALE);
    else if (blockIdx.z == 1) gemm_tile_body<1>(g_Xh, g_Wth[1], g_Kh, 1.0f);
    else                      gemm_tile_body<2>(g_Xh, g_Wth[2], g_Vth, 1.0f);
}

__global__ void __launch_bounds__(256) out_mma_kernel(float* __restrict__ out) {
    gemm_tile_body<0>(g_Ah, g_Wth[3], out, 1.0f);
}

// ---------------------------------------------------------------------------
// fp16 tensor-core causal flash attention (base-2 softmax, Q pre-scaled,
// P kept in registers, paired q-tiles for perfect load balance).
// grid (8 pairs, NH, BATCH), 256 threads = 8 warps x 16 rows.
// Each CTA processes q-tiles {15-x, x}: constant 34 key blocks per CTA.
// smem: sK[2][64][72] + sV[2][64][72] = 36864 bytes.
// ---------------------------------------------------------------------------
#define KBUF (64*HST)                    // halves per K/V buffer
#define ATTN_SMEM (4*KBUF*2)             // 36864 bytes

__device__ __forceinline__ void attn_load(const __half* __restrict__ Kg,
                                          const __half* __restrict__ Vt,
                                          uint32_t sKu, uint32_t sVu,
                                          int buf, int kbase, int tid) {
    const uint32_t dK = sKu + buf * KBUF * 2;
    const uint32_t dV = sVu + buf * KBUF * 2;
    #pragma unroll
    for (int i = 0; i < 2; i++) {
        int idx = tid + i * 256;         // 0..511 = 64 rows x 8 chunks
        int row = idx >> 3, c8 = idx & 7;
        uint32_t off = (row * HST + c8 * 8) * 2;
        cp_async16(dK + off, Kg + (size_t)(kbase + row) * DOUT + c8 * 8);
        cp_async16(dV + off, Vt + (size_t)row * SEQ + kbase + c8 * 8);
    }
}

__global__ void __launch_bounds__(256, 2) attn_f16_kernel() {
    extern __shared__ __half hsmem[];
    const uint32_t sKu = smem_u32(hsmem);
    const uint32_t sVu = sKu + 2 * KBUF * 2;

    const int h   = blockIdx.y;
    const int b   = blockIdx.z;
    const int tid = threadIdx.x;
    const int lane = tid & 31;
    const int wid  = tid >> 5;
    const int gr = lane >> 2, c2 = (lane & 3) * 2;

    const int lB_row = (lane & 7) + ((lane >> 4) & 1) * 8;
    const int lB_col = ((lane >> 3) & 1) * 8;

    const size_t rowbase = (size_t)b * SEQ;
    const int colbase = h * HD;
    const __half* Kg = g_Kh + rowbase * DOUT + colbase;
    const __half* Vt = g_Vth + (size_t)(b * NH + h) * HD * SEQ;

    const int wrow = wid * 16;
    const unsigned FULL = 0xffffffffu;

    #pragma unroll
    for (int seg = 0; seg < 2; seg++) {
        const int qt = seg == 0 ? (15 - (int)blockIdx.x) : (int)blockIdx.x;
        const int qbase = qt * 128;
        const int nkb = 2 * qt + 2;
        const int qg0 = qbase + wrow + gr;
        const int qg1 = qg0 + 8;

        // preload Q fragments (already scaled by 0.125*log2e)
        uint32_t qf[4][4];
        {
            const __half* Qg = g_Qh + (rowbase + qbase + wrow + gr) * DOUT + colbase + c2;
            #pragma unroll
            for (int ks = 0; ks < 4; ks++) {
                const __half* qp = Qg + ks * 16;
                qf[ks][0] = *(const uint32_t*)(qp);
                qf[ks][1] = *(const uint32_t*)(qp + 8 * DOUT);
                qf[ks][2] = *(const uint32_t*)(qp + 8);
                qf[ks][3] = *(const uint32_t*)(qp + 8 * DOUT + 8);
            }
        }

        float o[8][4] = {};
        float m0 = -1e30f, m1 = -1e30f, l0 = 0.f, l1 = 0.f;

        __syncthreads();                 // smem buffers free from previous segment
        attn_load(Kg, Vt, sKu, sVu, 0, 0, tid);
        cp_commit();

        for (int kb = 0; kb < nkb; kb++) {
            if (kb > 0) __syncthreads(); // buffer (kb+1)&1 readers (prev iter) done
            if (kb + 1 < nkb)
                attn_load(Kg, Vt, sKu, sVu, (kb + 1) & 1, (kb + 1) * 64, tid);
            cp_commit();
            cp_wait1();                  // block kb resident
            __syncthreads();

            const uint32_t cK = sKu + (kb & 1) * KBUF * 2;
            const uint32_t cV = sVu + (kb & 1) * KBUF * 2;
            const int kbase = kb * 64;

            // S = Q K^T  (already in base-2 log scale)
            float s[8][4] = {};
            #pragma unroll
            for (int ks = 0; ks < 4; ks++) {
                const int k0 = ks * 16;
                uint32_t bk[4][4];
                #pragma unroll
                for (int jj = 0; jj < 4; jj++)
                    ldsm_x4(bk[jj], cK + (((jj * 16 + lB_row) * HST + k0 + lB_col) << 1));
                #pragma unroll
                for (int j = 0; j < 8; j++)
                    mma_f16(s[j], qf[ks], &bk[j >> 1][(j & 1) * 2]);
            }

            // causal mask only near the diagonal
            if (kbase + 63 > qbase + wrow) {
                #pragma unroll
                for (int j = 0; j < 8; j++) {
                    const int col0 = kbase + j * 8 + c2;
                    if (col0     > qg0) s[j][0] = -1e30f;
                    if (col0 + 1 > qg0) s[j][1] = -1e30f;
                    if (col0     > qg1) s[j][2] = -1e30f;
                    if (col0 + 1 > qg1) s[j][3] = -1e30f;
                }
            }

            // row max
            float rx0 = -1e30f, rx1 = -1e30f;
            #pragma unroll
            for (int j = 0; j < 8; j++) {
                rx0 = fmaxf(rx0, fmaxf(s[j][0], s[j][1]));
                rx1 = fmaxf(rx1, fmaxf(s[j][2], s[j][3]));
            }
            rx0 = fmaxf(rx0, __shfl_xor_sync(FULL, rx0, 1));
            rx0 = fmaxf(rx0, __shfl_xor_sync(FULL, rx0, 2));
            rx1 = fmaxf(rx1, __shfl_xor_sync(FULL, rx1, 1));
            rx1 = fmaxf(rx1, __shfl_xor_sync(FULL, rx1, 2));

            const float nm0 = fmaxf(m0, rx0), nm1 = fmaxf(m1, rx1);
            float sum0 = 0.f, sum1 = 0.f;
            #pragma unroll
            for (int j = 0; j < 8; j++) {
                s[j][0] = ex2(s[j][0] - nm0);
                s[j][1] = ex2(s[j][1] - nm0);
                s[j][2] = ex2(s[j][2] - nm1);
                s[j][3] = ex2(s[j][3] - nm1);
                sum0 += s[j][0] + s[j][1];
                sum1 += s[j][2] + s[j][3];
            }
            sum0 += __shfl_xor_sync(FULL, sum0, 1);
            sum0 += __shfl_xor_sync(FULL, sum0, 2);
            sum1 += __shfl_xor_sync(FULL, sum1, 1);
            sum1 += __shfl_xor_sync(FULL, sum1, 2);

            const float a0 = ex2(m0 - nm0), a1 = ex2(m1 - nm1);
            l0 = l0 * a0 + sum0;  l1 = l1 * a1 + sum1;
            m0 = nm0;  m1 = nm1;
            #pragma unroll
            for (int j = 0; j < 8; j++) {
                o[j][0] *= a0; o[j][1] *= a0;
                o[j][2] *= a1; o[j][3] *= a1;
            }

            // O += P V with P converted in-register to A fragments.
            // A frag (m16n8k16, k=keys 16t..16t+15):
            //   a0 = S[gr][16t+c2, +1]       = s[2t][0..1]
            //   a1 = S[gr+8][16t+c2, +1]     = s[2t][2..3]
            //   a2 = S[gr][16t+8+c2, +1]     = s[2t+1][0..1]
            //   a3 = S[gr+8][16t+8+c2, +1]   = s[2t+1][2..3]
            #pragma unroll
            for (int t = 0; t < 4; t++) {
                const int k0 = t * 16;
                uint32_t ap[4] = { packh2(s[2*t][0],   s[2*t][1]),
                                   packh2(s[2*t][2],   s[2*t][3]),
                                   packh2(s[2*t+1][0], s[2*t+1][1]),
                                   packh2(s[2*t+1][2], s[2*t+1][3]) };
                uint32_t bv[4][4];
                #pragma unroll
                for (int jj = 0; jj < 4; jj++)
                    ldsm_x4(bv[jj], cV + (((jj * 16 + lB_row) * HST + k0 + lB_col) << 1));
                #pragma unroll
                for (int j = 0; j < 8; j++)
                    mma_f16(o[j], ap, &bv[j >> 1][(j & 1) * 2]);
            }
        }

        // normalize + fp16 store
        const float inv0 = 1.f / l0, inv1 = 1.f / l1;
        #pragma unroll
        for (int j = 0; j < 8; j++) {
            const int col = colbase + j * 8 + c2;
            *(__half2*)&g_Ah[(rowbase + qbase + wrow + gr) * DOUT + col] =
                __floats2half2_rn(o[j][0] * inv0, o[j][1] * inv0);
            *(__half2*)&g_Ah[(rowbase + qbase + wrow + gr + 8) * DOUT + col] =
                __floats2half2_rn(o[j][2] * inv1, o[j][3] * inv1);
        }
    }
}

// ---------------------------------------------------------------------------
extern "C" void kernel_launch(void* const* d_in, const int* in_sizes, int n_in,
                              void* d_out, int out_size) {
    (void)in_sizes; (void)n_in; (void)out_size;
    const float* x    = (const float*)d_in[0];
    const float* Wq   = (const float*)d_in[1];
    const float* Wk   = (const float*)d_in[2];
    const float* Wv   = (const float*)d_in[3];
    const float* Wout = (const float*)d_in[4];
    float* out = (float*)d_out;

    static bool attr_set = false;
    if (!attr_set) {
        cudaFuncSetAttribute(attn_f16_kernel,
                             cudaFuncAttributeMaxDynamicSharedMemorySize, ATTN_SMEM);
        cudaFuncSetAttribute(qkv_mma_kernel,
                             cudaFuncAttributeMaxDynamicSharedMemorySize, GEMM_SMEM);
        cudaFuncSetAttribute(out_mma_kernel,
                             cudaFuncAttributeMaxDynamicSharedMemorySize, GEMM_SMEM);
        attr_set = true;
    }

    x2h_kernel<<<(MTOT*DIN)/(256*4), 256>>>(x);
    wtrans_kernel<<<dim3(DOUT/32, DIN/32, 4), dim3(32, 8)>>>(Wq, Wk, Wv, Wout);

    qkv_mma_kernel<<<dim3(DOUT/128, MTOT/128, 3), 256, GEMM_SMEM>>>();

    attn_f16_kernel<<<dim3(SEQ/256, NH, BATCH), 256, ATTN_SMEM>>>();

    out_mma_kernel<<<dim3(DOUT/128, MTOT/128), 256, GEMM_SMEM>>>(out);
}